// round 12
// baseline (speedup 1.0000x reference)
#include <cuda_runtime.h>
#include <cuda_bf16.h>
#include <math.h>
#include <stdint.h>

#define BB 4
#define CC 256
#define HH 64
#define WW 64
#define PP (HH*WW)
#define GG 4

// ---------------- device scratch ----------------
__device__ float g_offset[BB*18*PP];
__device__ float g_xdense[BB*CC*PP];
__device__ float g_Bxinf[(size_t)BB*PP*256];   // x, px-major fp32 (for sampling)

// bf16 hi/lo weights
__device__ __nv_bfloat16 g_Achi[256*512], g_Aclo[256*512];         // w_cross
__device__ __nv_bfloat16 g_Ag2hi[256*64], g_Ag2lo[256*64];         // w_g2
__device__ __nv_bfloat16 g_Aohi[256*256], g_Aolo[256*256];         // w_out
__device__ __nv_bfloat16 g_wdefhi[GG*64*9*64], g_wdeflo[GG*64*9*64];   // [g][co][k*64+cg] = [g][co][576]
__device__ __nv_bfloat16 g_w1hi[64*9*256],    g_w1lo[64*9*256];        // [co][k][ci]
__device__ __nv_bfloat16 g_woffhi[32*9*256],  g_wofflo[32*9*256];      // [co pad32][k][ci]
// bf16 hi/lo activation B-operands [px][ch]
__device__ __nv_bfloat16 g_Bchi[(size_t)BB*PP*512], g_Bclo[(size_t)BB*PP*512];   // cross in
__device__ __nv_bfloat16 g_Bxhi[(size_t)BB*PP*256], g_Bxlo[(size_t)BB*PP*256];   // xdense
__device__ __nv_bfloat16 g_Bohi[(size_t)BB*PP*256], g_Bolo[(size_t)BB*PP*256];   // xdense*attn
__device__ __nv_bfloat16 g_Bxinhi[(size_t)BB*PP*256], g_Bxinlo[(size_t)BB*PP*256]; // x
// deform sampled columns: [(b*GG+g)*PP+px][k*64+cg]
__device__ __nv_bfloat16 g_Bdhi[(size_t)BB*GG*PP*576], g_Bdlo[(size_t)BB*GG*PP*576];

__device__ __forceinline__ float sigm(float v){ return 1.0f/(1.0f+expf(-v)); }

__device__ __forceinline__ void split2(float v, __nv_bfloat16 &h, __nv_bfloat16 &l){
    h = __float2bfloat16(v);
    l = __float2bfloat16(v - __bfloat162float(h));
}
__device__ __forceinline__ uint32_t pack_bf(__nv_bfloat16 lo, __nv_bfloat16 hi){
    return (uint32_t)__bfloat16_as_ushort(lo) | ((uint32_t)__bfloat16_as_ushort(hi) << 16);
}

__device__ __forceinline__ uint32_t smem_u32(const void* p){
    uint32_t a;
    asm("{ .reg .u64 tmp; cvta.to.shared.u64 tmp, %1; cvt.u32.u64 %0, tmp; }" : "=r"(a) : "l"(p));
    return a;
}

#define LDSM_X4(r, addr) \
    asm volatile("ldmatrix.sync.aligned.m8n8.x4.shared.b16 {%0,%1,%2,%3}, [%4];" \
        : "=r"((r)[0]), "=r"((r)[1]), "=r"((r)[2]), "=r"((r)[3]) : "r"(addr))
#define LDSM_X2(r, addr) \
    asm volatile("ldmatrix.sync.aligned.m8n8.x2.shared.b16 {%0,%1}, [%2];" \
        : "=r"((r)[0]), "=r"((r)[1]) : "r"(addr))
#define MMA16816(d, a, bfr) \
    asm volatile("mma.sync.aligned.m16n8k16.row.col.f32.bf16.bf16.f32 " \
        "{%0,%1,%2,%3}, {%4,%5,%6,%7}, {%8,%9}, {%0,%1,%2,%3};" \
        : "+f"((d)[0]), "+f"((d)[1]), "+f"((d)[2]), "+f"((d)[3]) \
        : "r"((a)[0]), "r"((a)[1]), "r"((a)[2]), "r"((a)[3]), "r"((bfr)[0]), "r"((bfr)[1]))

#define CP16(dst, src) \
    asm volatile("cp.async.cg.shared.global [%0], [%1], 16;" :: "r"(dst), "l"(src))
#define CP_COMMIT() asm volatile("cp.async.commit_group;" ::: "memory")
#define CP_WAIT0()  asm volatile("cp.async.wait_group 0;" ::: "memory")

// ---------------- merged weight split ----------------
__global__ void split_all(const float* __restrict__ w_cross,
                          const float* __restrict__ w_g2,
                          const float* __restrict__ w_out,
                          const float* __restrict__ w_def,
                          const float* __restrict__ w_g1,
                          const float* __restrict__ w_off){
    int id = blockIdx.x*256 + threadIdx.x;
    if (id < 131072){
        split2(w_cross[id], g_Achi[id], g_Aclo[id]); return;
    }
    id -= 131072;
    if (id < 16384){
        split2(w_g2[id], g_Ag2hi[id], g_Ag2lo[id]); return;
    }
    id -= 16384;
    if (id < 65536){
        split2(w_out[id], g_Aohi[id], g_Aolo[id]); return;
    }
    id -= 65536;
    if (id < 147456){
        int cg = id & 63;
        int r  = id >> 6;
        int k  = r % 9;
        int r2 = r / 9;
        int co = r2 & 63;
        int g  = r2 >> 6;
        split2(w_def[((g*64 + co)*64 + cg)*9 + k], g_wdefhi[id], g_wdeflo[id]);
        return;
    }
    id -= 147456;
    if (id < 147456){
        int ci = id & 255;
        int r  = id >> 8;
        int k  = r % 9;
        int co = r / 9;
        split2(w_g1[(co*256 + ci)*9 + k], g_w1hi[id], g_w1lo[id]);
        return;
    }
    id -= 147456;
    if (id < 73728){
        int ci = id & 255;
        int r  = id >> 8;
        int k  = r % 9;
        int co = r / 9;
        float v = (co < 18) ? w_off[(co*256 + ci)*9 + k] : 0.f;
        split2(v, g_woffhi[id], g_wofflo[id]);
    }
}

// ---------------- merged converter: [ch][px] fp32 -> [px][ch] hi/lo (+fp32 for x) -------
__global__ __launch_bounds__(256) void conv_rows2(const float* __restrict__ x,
                                                  const float* __restrict__ x_prev){
    __shared__ float tile[32][33];
    int px0 = blockIdx.x*32;
    int ch0 = blockIdx.y*32;
    int bz  = blockIdx.z;
    int b   = (bz < BB) ? bz : bz - BB;
    const float* src = (bz < BB) ? x : x_prev;
    int t   = threadIdx.x;
    #pragma unroll
    for (int i=0;i<4;i++){
        int e = t + i*256;
        int r = e >> 5, c = e & 31;
        tile[r][c] = src[((size_t)(b*256+ch0+r))*PP + px0 + c];
    }
    __syncthreads();
    #pragma unroll
    for (int i=0;i<4;i++){
        int e = t + i*256;
        int r = e >> 5, c = e & 31;
        float v = tile[c][r];
        __nv_bfloat16 h, l;
        split2(v, h, l);
        if (bz < BB){
            size_t o = ((size_t)(b*PP) + px0 + r)*256 + ch0 + c;
            g_Bxinhi[o]=h; g_Bxinlo[o]=l;
            g_Bxinf[o]=v;
        } else {
            size_t o = ((size_t)(b*PP) + px0 + r)*512 + 256 + ch0 + c;
            g_Bchi[o]=h; g_Bclo[o]=l;
        }
    }
}

// ================= offset conv: halo-B implicit GEMM, 128-px tile =================
#define CB_BSZ 37008           // 257 rows * 144
#define OFFC_SMEM (4*32*144 + 2*CB_BSZ)   // 92448
__global__ __launch_bounds__(256) void off_mma(const float* __restrict__ b_off){
    constexpr int ASZ  = 32*144;   // 4608
    constexpr int BOFF = 4*ASZ;    // 18432
    extern __shared__ char sm[];
    uint32_t su = smem_u32(sm);
    int t = threadIdx.x, lane = t & 31, wid = t >> 5;
    int wn = wid;                 // 8 warps x 16 px
    int px0 = blockIdx.x*128;
    int b   = blockIdx.y;

    float acc[2][2][4];
    #pragma unroll
    for (int i=0;i<2;i++)
        #pragma unroll
        for (int j=0;j<2;j++)
            #pragma unroll
            for (int q=0;q<4;q++) acc[i][j][q]=0.f;

    int l16 = lane & 15;
    uint32_t aoff_base = (uint32_t)((lane & 15)*144 + ((lane >> 4) << 3)*2);
    uint32_t bcol = (uint32_t)((l16 >> 3)*16);
    int rr[2], ry[2], rxc[2];
    #pragma unroll
    for (int na=0;na<2;na++){
        int r = wn*16 + na*8 + (l16 & 7);
        rr[na] = r;
        ry[na]  = (px0 + r) >> 6;
        rxc[na] = (px0 + r) & 63;
    }

    if (t < 9)        *(uint4*)(sm + BOFF + 256*144 + t*16) = make_uint4(0,0,0,0);
    else if (t < 18)  *(uint4*)(sm + BOFF + CB_BSZ + 256*144 + (t-9)*16) = make_uint4(0,0,0,0);

    for (int sub=0; sub<4; sub++){
        __syncthreads();
        #pragma unroll
        for (int i=0;i<8;i++){
            int e = t + i*256;
            int rt = e >> 3, c8 = e & 7;
            int p = px0 - 64 + rt;
            if ((unsigned)p < (unsigned)PP){
                size_t rb = ((size_t)(b*PP) + p)*256 + sub*64 + c8*8;
                uint32_t so = (uint32_t)(rt*144 + c8*16);
                CP16(su + BOFF + so,          g_Bxinhi + rb);
                CP16(su + BOFF + CB_BSZ + so, g_Bxinlo + rb);
            }
        }
        {
            int r = t >> 3, c8 = t & 7;
            uint32_t so = (uint32_t)(r*144 + c8*16);
            size_t go = (size_t)r*2304 + sub*64 + c8*8;
            CP16(su + so,       g_woffhi + go);
            CP16(su + ASZ + so, g_wofflo + go);
        }
        CP_COMMIT();

        for (int k=0;k<9;k++){
            CP_WAIT0();
            __syncthreads();
            if (k < 8){
                int st = (k+1) & 1;
                int r = t >> 3, c8 = t & 7;
                uint32_t so = (uint32_t)(st*2*ASZ + r*144 + c8*16);
                size_t go = (size_t)r*2304 + (k+1)*256 + sub*64 + c8*8;
                CP16(su + so,       g_woffhi + go);
                CP16(su + ASZ + so, g_wofflo + go);
                CP_COMMIT();
            }
            int dy = k/3 - 1, dx = k%3 - 1;
            int off = dy*WW + dx;
            uint32_t brow[2];
            #pragma unroll
            for (int na=0;na<2;na++){
                int yy = ry[na] + dy, xx = rxc[na] + dx;
                bool v = ((unsigned)yy < HH) && ((unsigned)xx < WW);
                brow[na] = v ? (uint32_t)((rr[na] + 64 + off)*144) : (uint32_t)(256*144);
            }
            uint32_t abase = su + (uint32_t)((k&1)*2*ASZ) + aoff_base;
            #pragma unroll
            for (int ks=0;ks<4;ks++){
                uint32_t bh[2][2], bl[2][2];
                #pragma unroll
                for (int na=0;na<2;na++){
                    uint32_t ba = su + BOFF + brow[na] + bcol + ks*32;
                    LDSM_X2(bh[na], ba);
                    LDSM_X2(bl[na], ba + CB_BSZ);
                }
                #pragma unroll
                for (int ma=0;ma<2;ma++){
                    uint32_t ao = abase + (uint32_t)(ma*16*144 + ks*32);
                    uint32_t ah[4], al[4];
                    LDSM_X4(ah, ao);
                    LDSM_X4(al, ao + ASZ);
                    #pragma unroll
                    for (int na=0;na<2;na++){
                        MMA16816(acc[ma][na], ah, bh[na]);
                        MMA16816(acc[ma][na], al, bh[na]);
                        MMA16816(acc[ma][na], ah, bl[na]);
                    }
                }
            }
        }
    }

    #pragma unroll
    for (int ma=0;ma<2;ma++){
        int r0 = ma*16 + (lane>>2);
        int r1 = r0 + 8;
        #pragma unroll
        for (int na=0;na<2;na++){
            int px = px0 + wn*16 + na*8 + ((lane&3)<<1);
            if (r0 < 18){
                float bb = b_off[r0];
                *(float2*)&g_offset[((size_t)(b*18 + r0))*PP + px] =
                    make_float2(acc[ma][na][0]+bb, acc[ma][na][1]+bb);
            }
            if (r1 < 18){
                float bb = b_off[r1];
                *(float2*)&g_offset[((size_t)(b*18 + r1))*PP + px] =
                    make_float2(acc[ma][na][2]+bb, acc[ma][na][3]+bb);
            }
        }
    }
}

// ================= deform sampling from fp32 px-major g_Bxinf (coalesced, low ALU) =======
__global__ __launch_bounds__(256) void sample_def(){
    int t = threadIdx.x;
    int pxl = t >> 3, c8 = t & 7;
    int px0 = blockIdx.x*32;
    int k  = blockIdx.y;
    int gz = blockIdx.z;
    int g = gz & 3, b = gz >> 2;
    int px = px0 + pxl;
    int y = px >> 6, xc = px & 63;

    float dy = g_offset[(b*18 + 2*k  )*PP + px];
    float dx = g_offset[(b*18 + 2*k+1)*PP + px];
    float py  = (float)y  + (float)(k/3 - 1) + dy;
    float pxx = (float)xc + (float)(k%3 - 1) + dx;
    float fy = floorf(py), fx = floorf(pxx);
    int y0 = (int)fy, x0 = (int)fx;
    float wy = py - fy, wx = pxx - fx;
    float w00 = (1.f-wy)*(1.f-wx);
    float w01 = (1.f-wy)*wx;
    float w10 = wy*(1.f-wx);
    float w11 = wy*wx;
    bool vy0 = (y0 >= 0) && (y0 < HH);
    bool vy1 = (y0 >= -1) && (y0 < HH-1);
    bool vx0 = (x0 >= 0) && (x0 < WW);
    bool vx1 = (x0 >= -1) && (x0 < WW-1);
    float m00 = (vy0 && vx0) ? w00 : 0.f;
    float m01 = (vy0 && vx1) ? w01 : 0.f;
    float m10 = (vy1 && vx0) ? w10 : 0.f;
    float m11 = (vy1 && vx1) ? w11 : 0.f;
    int cy0 = min(max(y0,0),HH-1), cy1 = min(max(y0+1,0),HH-1);
    int cx0 = min(max(x0,0),WW-1), cx1 = min(max(x0+1,0),WW-1);
    const float* base = g_Bxinf + ((size_t)(b*PP))*256 + g*64 + c8*8;
    const float* r00 = base + (size_t)(cy0*WW+cx0)*256;
    const float* r01 = base + (size_t)(cy0*WW+cx1)*256;
    const float* r10 = base + (size_t)(cy1*WW+cx0)*256;
    const float* r11 = base + (size_t)(cy1*WW+cx1)*256;

    float4 a00 = *(const float4*)(r00);
    float4 b00 = *(const float4*)(r00+4);
    float4 a01 = *(const float4*)(r01);
    float4 b01 = *(const float4*)(r01+4);
    float4 a10 = *(const float4*)(r10);
    float4 b10 = *(const float4*)(r10+4);
    float4 a11 = *(const float4*)(r11);
    float4 b11 = *(const float4*)(r11+4);

    float v[8];
    v[0] = m00*a00.x + m01*a01.x + m10*a10.x + m11*a11.x;
    v[1] = m00*a00.y + m01*a01.y + m10*a10.y + m11*a11.y;
    v[2] = m00*a00.z + m01*a01.z + m10*a10.z + m11*a11.z;
    v[3] = m00*a00.w + m01*a01.w + m10*a10.w + m11*a11.w;
    v[4] = m00*b00.x + m01*b01.x + m10*b10.x + m11*b11.x;
    v[5] = m00*b00.y + m01*b01.y + m10*b10.y + m11*b11.y;
    v[6] = m00*b00.z + m01*b01.z + m10*b10.z + m11*b11.z;
    v[7] = m00*b00.w + m01*b01.w + m10*b10.w + m11*b11.w;

    uint32_t hi[4], lo[4];
    #pragma unroll
    for (int j=0;j<8;j+=2){
        __nv_bfloat16 h0,l0,h1,l1;
        split2(v[j],h0,l0); split2(v[j+1],h1,l1);
        hi[j>>1] = pack_bf(h0,h1);
        lo[j>>1] = pack_bf(l0,l1);
    }
    size_t o = ((size_t)((b*GG+g)*PP) + px)*576 + k*64 + c8*8;
    *(uint4*)(g_Bdhi + o) = make_uint4(hi[0],hi[1],hi[2],hi[3]);
    *(uint4*)(g_Bdlo + o) = make_uint4(lo[0],lo[1],lo[2],lo[3]);
}

// ================= deform GEMM: 64co x 128px, K=576 (cp.async 2-stage) =================
#define DG_STAGE 55296
#define DG_SMEM (2*DG_STAGE)   // 110592

__device__ __forceinline__ void dg_copy(uint32_t su, int s, int c, int t,
    const __nv_bfloat16* Ab, const __nv_bfloat16* Alb,
    const __nv_bfloat16* Bb, const __nv_bfloat16* Blb){
    uint32_t base = su + s*DG_STAGE;
    #pragma unroll
    for (int i=0;i<2;i++){
        int e = t + i*256;
        int r = e >> 3, c8 = e & 7;
        uint32_t so = (uint32_t)(r*144 + c8*16);
        size_t go = (size_t)r*576 + c*64 + c8*8;
        CP16(base + so,        Ab  + go);
        CP16(base + 9216 + so, Alb + go);
    }
    #pragma unroll
    for (int i=0;i<4;i++){
        int e = t + i*256;
        int r = e >> 3, c8 = e & 7;
        uint32_t so = (uint32_t)(r*144 + c8*16);
        size_t go = (size_t)r*576 + c*64 + c8*8;
        CP16(base + 18432 + so, Bb  + go);
        CP16(base + 36864 + so, Blb + go);
    }
}

__global__ __launch_bounds__(256) void def_gemm(){
    extern __shared__ char sm[];
    uint32_t su = smem_u32(sm);
    int t = threadIdx.x, lane = t & 31, wid = t >> 5;
    int wm = wid >> 2, wn = wid & 3;
    int px0 = blockIdx.x*128;
    int g   = blockIdx.y;
    int b   = blockIdx.z;

    const __nv_bfloat16* Ab  = g_wdefhi + (size_t)g*64*576;
    const __nv_bfloat16* Alb = g_wdeflo + (size_t)g*64*576;
    const __nv_bfloat16* Bb  = g_Bdhi + ((size_t)((b*GG+g)*PP) + px0)*576;
    const __nv_bfloat16* Blb = g_Bdlo + ((size_t)((b*GG+g)*PP) + px0)*576;

    float acc[2][4][4];
    #pragma unroll
    for (int i=0;i<2;i++)
        #pragma unroll
        for (int j=0;j<4;j++)
            #pragma unroll
            for (int q=0;q<4;q++) acc[i][j][q]=0.f;

    int l16 = lane & 15;
    uint32_t aoff_base = (uint32_t)((wm*32 + (lane & 15))*144 + ((lane >> 4) << 3)*2);
    uint32_t boff_base = (uint32_t)((wn*32 + (l16 & 7))*144 + ((l16 >> 3) << 3)*2);

    dg_copy(su, 0, 0, t, Ab, Alb, Bb, Blb);
    CP_COMMIT();

    for (int c = 0; c < 9; c++){
        CP_WAIT0();
        __syncthreads();
        if (c+1 < 9){ dg_copy(su, (c+1)&1, c+1, t, Ab, Alb, Bb, Blb); CP_COMMIT(); }
        uint32_t sb = su + (c&1)*DG_STAGE;
        #pragma unroll
        for (int ks=0;ks<4;ks++){
            uint32_t bh[4][2], bl[4][2];
            #pragma unroll
            for (int na=0;na<4;na++){
                uint32_t boff = boff_base + (uint32_t)(na*8*144 + ks*32);
                LDSM_X2(bh[na], sb + 18432 + boff);
                LDSM_X2(bl[na], sb + 36864 + boff);
            }
            #pragma unroll
            for (int ma=0;ma<2;ma++){
                uint32_t ao = sb + aoff_base + (uint32_t)(ma*16*144 + ks*32);
                uint32_t ah[4], al[4];
                LDSM_X4(ah, ao);
                LDSM_X4(al, ao + 9216);
                #pragma unroll
                for (int na=0;na<4;na++){
                    MMA16816(acc[ma][na], ah, bh[na]);
                    MMA16816(acc[ma][na], al, bh[na]);
                    MMA16816(acc[ma][na], ah, bl[na]);
                }
            }
        }
    }

    // epilogue: transpose to [px][64] hi/lo in smem, write g_Bc slice [g*64, g*64+64)
    __syncthreads();
    #pragma unroll
    for (int ma=0;ma<2;ma++){
        int r0 = wm*32 + ma*16 + (lane>>2);
        int r1 = r0 + 8;
        #pragma unroll
        for (int na=0;na<4;na++){
            int px = wn*32 + na*8 + ((lane&3)<<1);
            __nv_bfloat16 h,l;
            split2(acc[ma][na][0],h,l);
            *(__nv_bfloat16*)(sm + px*144 + r0*2) = h;
            *(__nv_bfloat16*)(sm + 18432 + px*144 + r0*2) = l;
            split2(acc[ma][na][1],h,l);
            *(__nv_bfloat16*)(sm + (px+1)*144 + r0*2) = h;
            *(__nv_bfloat16*)(sm + 18432 + (px+1)*144 + r0*2) = l;
            split2(acc[ma][na][2],h,l);
            *(__nv_bfloat16*)(sm + px*144 + r1*2) = h;
            *(__nv_bfloat16*)(sm + 18432 + px*144 + r1*2) = l;
            split2(acc[ma][na][3],h,l);
            *(__nv_bfloat16*)(sm + (px+1)*144 + r1*2) = h;
            *(__nv_bfloat16*)(sm + 18432 + (px+1)*144 + r1*2) = l;
        }
    }
    __syncthreads();
    #pragma unroll
    for (int i=0;i<4;i++){
        int e = t + i*256;
        int r = e >> 3, c8 = e & 7;
        size_t o = ((size_t)(b*PP) + px0 + r)*512 + g*64 + c8*8;
        *(uint4*)(g_Bchi + o) = *(const uint4*)(sm + r*144 + c8*16);
        *(uint4*)(g_Bclo + o) = *(const uint4*)(sm + 18432 + r*144 + c8*16);
    }
}

// ---------------- generic mma GEMM (cp.async 2-stage) 128co x 128px ----------------
#define T_BYTES  (128*144)              // 18432
#define G_STAGE  (4*T_BYTES)            // 73728
#define SMEM_GEMM (2*G_STAGE)           // 147456

template<int K>
__device__ __forceinline__ void gemm_copy(uint32_t su, int s, int c, int t,
    const __nv_bfloat16* Ab, const __nv_bfloat16* Alb,
    const __nv_bfloat16* Bb, const __nv_bfloat16* Blb){
    uint32_t base = su + s*G_STAGE;
    #pragma unroll
    for (int i=0;i<4;i++){
        int e = t + i*256;
        int r = e >> 3, c8 = e & 7;
        uint32_t so = (uint32_t)(r*144 + c8*16);
        size_t go = (size_t)r*K + c*64 + c8*8;
        CP16(base + so,             Ab  + go);
        CP16(base + T_BYTES + so,   Alb + go);
        CP16(base + 2*T_BYTES + so, Bb  + go);
        CP16(base + 3*T_BYTES + so, Blb + go);
    }
}

template<int MODE>
__global__ __launch_bounds__(256) void gemm_mma(const float* __restrict__ bias,
                                                const float* __restrict__ gamma,
                                                const float* __restrict__ beta,
                                                const float* __restrict__ mean,
                                                const float* __restrict__ var,
                                                const float* __restrict__ resid,
                                                float* __restrict__ outp){
    constexpr int K = (MODE==0) ? 512 : 256;
    constexpr int CHUNKS = K/64;
    extern __shared__ char smem[];
    uint32_t su = smem_u32(smem);
    int t    = threadIdx.x;
    int lane = t & 31;
    int wid  = t >> 5;
    int wm   = wid >> 2;
    int wn   = wid & 3;
    int px0  = blockIdx.x*128;
    int co0  = blockIdx.y*128;
    int b    = blockIdx.z;

    const __nv_bfloat16* Ahi = (MODE==0) ? g_Achi : g_Aohi;
    const __nv_bfloat16* Alo = (MODE==0) ? g_Aclo : g_Aolo;
    const __nv_bfloat16* Bhi = (MODE==0) ? g_Bchi : g_Bohi;
    const __nv_bfloat16* Blo = (MODE==0) ? g_Bclo : g_Bolo;

    const __nv_bfloat16* Ab  = Ahi + (size_t)co0*K;
    const __nv_bfloat16* Alb = Alo + (size_t)co0*K;
    const __nv_bfloat16* Bb  = Bhi + ((size_t)(b*PP) + px0)*K;
    const __nv_bfloat16* Blb = Blo + ((size_t)(b*PP) + px0)*K;

    float acc[4][4][4];
    #pragma unroll
    for (int i=0;i<4;i++)
        #pragma unroll
        for (int j=0;j<4;j++)
            #pragma unroll
            for (int q=0;q<4;q++) acc[i][j][q] = 0.f;

    int l16 = lane & 15;
    uint32_t aoff_base = (uint32_t)((wm*64 + (lane & 15))*144 + ((lane >> 4) << 3)*2);
    uint32_t boff_base = (uint32_t)((wn*32 + (l16 & 7))*144 + ((l16 >> 3) << 3)*2);

    gemm_copy<K>(su, 0, 0, t, Ab, Alb, Bb, Blb);
    CP_COMMIT();

    for (int c = 0; c < CHUNKS; c++){
        CP_WAIT0();
        __syncthreads();
        if (c+1 < CHUNKS){ gemm_copy<K>(su, (c+1)&1, c+1, t, Ab, Alb, Bb, Blb); CP_COMMIT(); }
        uint32_t sb = su + (c&1)*G_STAGE;
        #pragma unroll
        for (int ks = 0; ks < 4; ks++){
            uint32_t bh[4][2], bl[4][2];
            #pragma unroll
            for (int na=0;na<4;na++){
                uint32_t boff = boff_base + (uint32_t)(na*8*144 + ks*32);
                LDSM_X2(bh[na], sb + 2*T_BYTES + boff);
                LDSM_X2(bl[na], sb + 3*T_BYTES + boff);
            }
            #pragma unroll
            for (int ma=0;ma<4;ma++){
                uint32_t aoff = aoff_base + (uint32_t)(ma*16*144 + ks*32);
                uint32_t ah[4], al[4];
                LDSM_X4(ah, sb + aoff);
                LDSM_X4(al, sb + T_BYTES + aoff);
                #pragma unroll
                for (int na=0;na<4;na++){
                    MMA16816(acc[ma][na], ah, bh[na]);
                    MMA16816(acc[ma][na], al, bh[na]);
                    MMA16816(acc[ma][na], ah, bl[na]);
                }
            }
        }
    }

    if (MODE == 2){
        #pragma unroll
        for (int ma=0;ma<4;ma++){
            int r0 = co0 + wm*64 + ma*16 + (lane>>2);
            int r1 = r0 + 8;
            float bb0 = bias[r0], bb1 = bias[r1];
            float iv0 = gamma[r0]*rsqrtf(var[r0]+1e-5f), sh0 = beta[r0]-mean[r0]*iv0;
            float iv1 = gamma[r1]*rsqrtf(var[r1]+1e-5f), sh1 = beta[r1]-mean[r1]*iv1;
            #pragma unroll
            for (int na=0;na<4;na++){
                int px = px0 + wn*32 + na*8 + ((lane&3)<<1);
                size_t i0 = ((size_t)(b*CC + r0))*PP + px;
                size_t i1 = ((size_t)(b*CC + r1))*PP + px;
                float2 rv0 = *(const float2*)&resid[i0];
                float2 rv1 = *(const float2*)&resid[i1];
                float v0 = (acc[ma][na][0]+bb0)*iv0 + sh0;
                float v1 = (acc[ma][na][1]+bb0)*iv0 + sh0;
                float v2 = (acc[ma][na][2]+bb1)*iv1 + sh1;
                float v3 = (acc[ma][na][3]+bb1)*iv1 + sh1;
                *(float2*)&outp[i0] = make_float2(rv0.x + v0*sigm(v0), rv0.y + v1*sigm(v1));
                *(float2*)&outp[i1] = make_float2(rv1.x + v2*sigm(v2), rv1.y + v3*sigm(v3));
            }
        }
        return;
    }

    // MODE 0: write g_xdense fp32 + transposed bf16 hi/lo g_Bx slice
    __syncthreads();
    #pragma unroll
    for (int ma=0;ma<4;ma++){
        int r0 = wm*64 + ma*16 + (lane>>2);
        int r1 = r0 + 8;
        int gr0 = co0 + r0, gr1 = co0 + r1;
        #pragma unroll
        for (int na=0;na<4;na++){
            int px = wn*32 + na*8 + ((lane&3)<<1);
            float d0 = acc[ma][na][0], d1 = acc[ma][na][1];
            float d2 = acc[ma][na][2], d3 = acc[ma][na][3];
            size_t i0 = ((size_t)(b*CC + gr0))*PP + px0 + px;
            size_t i1 = ((size_t)(b*CC + gr1))*PP + px0 + px;
            *(float2*)&g_xdense[i0] = make_float2(d0, d1);
            *(float2*)&g_xdense[i1] = make_float2(d2, d3);
            __nv_bfloat16 h,l;
            split2(d0,h,l);
            *(__nv_bfloat16*)(smem + px*272 + r0*2) = h;
            *(__nv_bfloat16*)(smem + 34816 + px*272 + r0*2) = l;
            split2(d1,h,l);
            *(__nv_bfloat16*)(smem + (px+1)*272 + r0*2) = h;
            *(__nv_bfloat16*)(smem + 34816 + (px+1)*272 + r0*2) = l;
            split2(d2,h,l);
            *(__nv_bfloat16*)(smem + px*272 + r1*2) = h;
            *(__nv_bfloat16*)(smem + 34816 + px*272 + r1*2) = l;
            split2(d3,h,l);
            *(__nv_bfloat16*)(smem + (px+1)*272 + r1*2) = h;
            *(__nv_bfloat16*)(smem + 34816 + (px+1)*272 + r1*2) = l;
        }
    }
    __syncthreads();
    #pragma unroll
    for (int i=0;i<8;i++){
        int e = t + i*256;
        int r = e >> 4, c16 = e & 15;
        size_t o = ((size_t)(b*PP) + px0 + r)*256 + co0 + c16*8;
        *(uint4*)(g_Bxhi + o) = *(const uint4*)(smem + r*272 + c16*16);
        *(uint4*)(g_Bxlo + o) = *(const uint4*)(smem + 34816 + r*272 + c16*16);
    }
}

// ================ g1 conv + g2 attention fused ================
#define G1F_SMEM (4*64*144 + 2*CB_BSZ)   // 110880
__global__ __launch_bounds__(256) void g1_fused(const float* __restrict__ bias,
                                                const float* __restrict__ gamma,
                                                const float* __restrict__ beta,
                                                const float* __restrict__ mean,
                                                const float* __restrict__ var,
                                                const float* __restrict__ b_g2){
    constexpr int ASZ  = 64*144;   // 9216
    constexpr int BOFF = 4*ASZ;    // 36864
    extern __shared__ char sm[];
    uint32_t su = smem_u32(sm);
    int t = threadIdx.x, lane = t & 31, wid = t >> 5;
    int wm = wid >> 2, wn = wid & 3;
    int px0 = blockIdx.x*128;
    int b   = blockIdx.y;

    int l16 = lane & 15;
    uint32_t aoff_base = (uint32_t)((wm*32 + (lane & 15))*144 + ((lane >> 4) << 3)*2);
    uint32_t bcol = (uint32_t)((l16 >> 3)*16);
    int rr[4], ry[4], rxc[4];
    #pragma unroll
    for (int na=0;na<4;na++){
        int r = wn*32 + na*8 + (l16 & 7);
        rr[na] = r;
        ry[na]  = (px0 + r) >> 6;
        rxc[na] = (px0 + r) & 63;
    }

    float acc[2][4][4];
    #pragma unroll
    for (int i=0;i<2;i++)
        #pragma unroll
        for (int j=0;j<4;j++)
            #pragma unroll
            for (int q=0;q<4;q++) acc[i][j][q]=0.f;

    if (t < 9)        *(uint4*)(sm + BOFF + 256*144 + t*16) = make_uint4(0,0,0,0);
    else if (t < 18)  *(uint4*)(sm + BOFF + CB_BSZ + 256*144 + (t-9)*16) = make_uint4(0,0,0,0);

    for (int sub=0; sub<4; sub++){
        __syncthreads();
        #pragma unroll
        for (int i=0;i<8;i++){
            int e = t + i*256;
            int rt = e >> 3, c8 = e & 7;
            int p = px0 - 64 + rt;
            if ((unsigned)p < (unsigned)PP){
                size_t rb = ((size_t)(b*PP) + p)*256 + sub*64 + c8*8;
                uint32_t so = (uint32_t)(rt*144 + c8*16);
                CP16(su + BOFF + so,          g_Bxhi + rb);
                CP16(su + BOFF + CB_BSZ + so, g_Bxlo + rb);
            }
        }
        #pragma unroll
        for (int i=0;i<2;i++){
            int e = t + i*256;
            int r = e >> 3, c8 = e & 7;
            uint32_t so = (uint32_t)(r*144 + c8*16);
            size_t go = (size_t)r*2304 + sub*64 + c8*8;
            CP16(su + so,       g_w1hi + go);
            CP16(su + ASZ + so, g_w1lo + go);
        }
        CP_COMMIT();

        for (int k=0;k<9;k++){
            CP_WAIT0();
            __syncthreads();
            if (k < 8){
                int st = (k+1) & 1;
                #pragma unroll
                for (int i=0;i<2;i++){
                    int e = t + i*256;
                    int r = e >> 3, c8 = e & 7;
                    uint32_t so = (uint32_t)(st*2*ASZ + r*144 + c8*16);
                    size_t go = (size_t)r*2304 + (k+1)*256 + sub*64 + c8*8;
                    CP16(su + so,       g_w1hi + go);
                    CP16(su + ASZ + so, g_w1lo + go);
                }
                CP_COMMIT();
            }
            int dy = k/3 - 1, dx = k%3 - 1;
            int off = dy*WW + dx;
            uint32_t brow[4];
            #pragma unroll
            for (int na=0;na<4;na++){
                int yy = ry[na] + dy, xx = rxc[na] + dx;
                bool v = ((unsigned)yy < HH) && ((unsigned)xx < WW);
                brow[na] = v ? (uint32_t)((rr[na] + 64 + off)*144) : (uint32_t)(256*144);
            }
            uint32_t abase = su + (uint32_t)((k&1)*2*ASZ) + aoff_base;
            #pragma unroll
            for (int ks=0;ks<4;ks++){
                uint32_t bh[4][2], bl[4][2];
                #pragma unroll
                for (int na=0;na<4;na++){
                    uint32_t ba = su + BOFF + brow[na] + bcol + ks*32;
                    LDSM_X2(bh[na], ba);
                    LDSM_X2(bl[na], ba + CB_BSZ);
                }
                #pragma unroll
                for (int ma=0;ma<2;ma++){
                    uint32_t ao = abase + (uint32_t)(ma*16*144 + ks*32);
                    uint32_t ah[4], al[4];
                    LDSM_X4(ah, ao);
                    LDSM_X4(al, ao + ASZ);
                    #pragma unroll
                    for (int na=0;na<4;na++){
                        MMA16816(acc[ma][na], ah, bh[na]);
                        MMA16816(acc[ma][na], al, bh[na]);
                        MMA16816(acc[ma][na], ah, bl[na]);
                    }
                }
            }
        }
    }

    // phase A epilogue: bn+silu -> a-tile staged at [0,36864) [px][64] hi/lo
    __syncthreads();
    #pragma unroll
    for (int ma=0;ma<2;ma++){
        int r0 = wm*32 + ma*16 + (lane>>2);
        int r1 = r0 + 8;
        float bb0 = bias[r0], bb1 = bias[r1];
        float iv0 = gamma[r0]*rsqrtf(var[r0]+1e-5f), sh0 = beta[r0]-mean[r0]*iv0;
        float iv1 = gamma[r1]*rsqrtf(var[r1]+1e-5f), sh1 = beta[r1]-mean[r1]*iv1;
        #pragma unroll
        for (int na=0;na<4;na++){
            int px = wn*32 + na*8 + ((lane&3)<<1);
            float v0 = (acc[ma][na][0]+bb0)*iv0 + sh0; v0 = v0*sigm(v0);
            float v1 = (acc[ma][na][1]+bb0)*iv0 + sh0; v1 = v1*sigm(v1);
            float v2 = (acc[ma][na][2]+bb1)*iv1 + sh1; v2 = v2*sigm(v2);
            float v3 = (acc[ma][na][3]+bb1)*iv1 + sh1; v3 = v3*sigm(v3);
            __nv_bfloat16 h,l;
            split2(v0,h,l);
            *(__nv_bfloat16*)(sm + px*144 + r0*2) = h;
            *(__nv_bfloat16*)(sm + 18432 + px*144 + r0*2) = l;
            split2(v1,h,l);
            *(__nv_bfloat16*)(sm + (px+1)*144 + r0*2) = h;
            *(__nv_bfloat16*)(sm + 18432 + (px+1)*144 + r0*2) = l;
            split2(v2,h,l);
            *(__nv_bfloat16*)(sm + px*144 + r1*2) = h;
            *(__nv_bfloat16*)(sm + 18432 + px*144 + r1*2) = l;
            split2(v3,h,l);
            *(__nv_bfloat16*)(sm + (px+1)*144 + r1*2) = h;
            *(__nv_bfloat16*)(sm + 18432 + (px+1)*144 + r1*2) = l;
        }
    }

    // ---- phase B: attn GEMM (K=64), 2 passes of 128 co ----
    uint32_t aoff2_base = (uint32_t)((wm*64 + (lane & 15))*144 + ((lane >> 4) << 3)*2);
    uint32_t boff2_base = (uint32_t)((wn*32 + (l16 & 7))*144 + ((l16 >> 3) << 3)*2);

    for (int p=0; p<2; p++){
        __syncthreads();
        #pragma unroll
        for (int i=0;i<4;i++){
            int e = t + i*256;
            int r = e >> 3, c8 = e & 7;
            uint32_t so = (uint32_t)(r*144 + c8*16);
            size_t go = (size_t)(p*128 + r)*64 + c8*8;
            CP16(su + BOFF + so,         g_Ag2hi + go);
            CP16(su + BOFF + 18432 + so, g_Ag2lo + go);
        }
        CP_COMMIT(); CP_WAIT0();
        __syncthreads();

        float acc2[4][4][4];
        #pragma unroll
        for (int i=0;i<4;i++)
            #pragma unroll
            for (int j=0;j<4;j++)
                #pragma unroll
                for (int q=0;q<4;q++) acc2[i][j][q]=0.f;

        #pragma unroll
        for (int ks=0;ks<4;ks++){
            uint32_t bh[4][2], bl[4][2];
            #pragma unroll
            for (int na=0;na<4;na++){
                uint32_t boff = boff2_base + (uint32_t)(na*8*144 + ks*32);
                LDSM_X2(bh[na], su + boff);
                LDSM_X2(bl[na], su + 18432 + boff);
            }
            #pragma unroll
            for (int ma=0;ma<4;ma++){
                uint32_t ao = su + BOFF + aoff2_base + (uint32_t)(ma*16*144 + ks*32);
                uint32_t ah[4], al[4];
                LDSM_X4(ah, ao);
                LDSM_X4(al, ao + 18432);
                #pragma unroll
                for (int na=0;na<4;na++){
                    MMA16816(acc2[ma][na], ah, bh[na]);
                    MMA16816(acc2[ma][na], al, bh[na]);
                    MMA16816(acc2[ma][na], ah, bl[na]);
                }
            }
        }

        __syncthreads();
        #pragma unroll
        for (int ma=0;ma<4;ma++){
            int r0 = wm*64 + ma*16 + (lane>>2);
            int r1 = r0 + 8;
            int gr0 = p*128 + r0, gr1 = p*128 + r1;
            float bb0 = b_g2[gr0], bb1 = b_g2[gr1];
            #pragma unroll
            for (int na=0;na<4;na++){
                int px = wn*32 + na*8 + ((lane&3)<<1);
                size_t i0 = ((size_t)(b*CC + gr0))*PP + px0 + px;
                size_t i1 = ((size_t)(b*CC + gr1))*PP + px0 + px;
                float2 x0 = *(const float2*)&g_xdense[i0];
                float2 x1 = *(const float2*)&g_xdense[i1];
                float v0 = x0.x * sigm(acc2[ma][na][0]+bb0);
                float v1 = x0.y * sigm(acc2[ma][na][1]+bb0);
                float v2 = x1.x * sigm(acc2[ma][na][2]+bb1);
                float v3 = x1.y * sigm(acc2[ma][na][3]+bb1);
                __nv_bfloat16 h,l;
                split2(v0,h,l);
                *(__nv_bfloat16*)(sm + BOFF + px*272 + r0*2) = h;
                *(__nv_bfloat16*)(sm + BOFF + 34816 + px*272 + r0*2) = l;
                split2(v1,h,l);
                *(__nv_bfloat16*)(sm + BOFF + (px+1)*272 + r0*2) = h;
                *(__nv_bfloat16*)(sm + BOFF + 34816 + (px+1)*272 + r0*2) = l;
                split2(v2,h,l);
                *(__nv_bfloat16*)(sm + BOFF + px*272 + r1*2) = h;
                *(__nv_bfloat16*)(sm + BOFF + 34816 + px*272 + r1*2) = l;
                split2(v3,h,l);
                *(__nv_bfloat16*)(sm + BOFF + (px+1)*272 + r1*2) = h;
                *(__nv_bfloat16*)(sm + BOFF + 34816 + (px+1)*272 + r1*2) = l;
            }
        }
        __syncthreads();
        #pragma unroll
        for (int i=0;i<8;i++){
            int e = t + i*256;
            int r = e >> 4, c16 = e & 15;
            size_t o = ((size_t)(b*PP) + px0 + r)*256 + p*128 + c16*8;
            *(uint4*)(g_Bohi + o) = *(const uint4*)(sm + BOFF + r*272 + c16*16);
            *(uint4*)(g_Bolo + o) = *(const uint4*)(sm + BOFF + 34816 + r*272 + c16*16);
        }
    }
}

// ---------------- launch ----------------
extern "C" void kernel_launch(void* const* d_in, const int* in_sizes, int n_in,
                              void* d_out, int out_size){
    const float* x       = (const float*)d_in[0];
    const float* x_prev  = (const float*)d_in[1];
    const float* w_off   = (const float*)d_in[2];
    const float* b_off   = (const float*)d_in[3];
    const float* w_def   = (const float*)d_in[4];
    const float* w_cross = (const float*)d_in[5];
    const float* w_g1    = (const float*)d_in[6];
    const float* b_g1    = (const float*)d_in[7];
    const float* g1_gamma= (const float*)d_in[8];
    const float* g1_beta = (const float*)d_in[9];
    const float* g1_mean = (const float*)d_in[10];
    const float* g1_var  = (const float*)d_in[11];
    const float* w_g2    = (const float*)d_in[12];
    const float* b_g2    = (const float*)d_in[13];
    const float* w_out   = (const float*)d_in[14];
    const float* b_out   = (const float*)d_in[15];
    const float* o_gamma = (const float*)d_in[16];
    const float* o_beta  = (const float*)d_in[17];
    const float* o_mean  = (const float*)d_in[18];
    const float* o_var   = (const float*)d_in[19];
    float* out = (float*)d_out;

    cudaFuncSetAttribute(gemm_mma<0>, cudaFuncAttributeMaxDynamicSharedMemorySize, SMEM_GEMM);
    cudaFuncSetAttribute(gemm_mma<2>, cudaFuncAttributeMaxDynamicSharedMemorySize, SMEM_GEMM);
    cudaFuncSetAttribute(def_gemm,    cudaFuncAttributeMaxDynamicSharedMemorySize, DG_SMEM);
    cudaFuncSetAttribute(off_mma,     cudaFuncAttributeMaxDynamicSharedMemorySize, OFFC_SMEM);
    cudaFuncSetAttribute(g1_fused,    cudaFuncAttributeMaxDynamicSharedMemorySize, G1F_SMEM);

    split_all<<<2272, 256>>>(w_cross, w_g2, w_out, w_def, w_g1, w_off);
    conv_rows2<<<dim3(PP/32, 8, 2*BB), 256>>>(x, x_prev);

    off_mma<<<dim3(PP/128, BB), 256, OFFC_SMEM>>>(b_off);
    sample_def<<<dim3(PP/32, 9, GG*BB), 256>>>();
    def_gemm<<<dim3(PP/128, GG, BB), 256, DG_SMEM>>>();

    gemm_mma<0><<<dim3(PP/128, 2, BB), 256, SMEM_GEMM>>>(nullptr,nullptr,nullptr,nullptr,nullptr,nullptr,nullptr);
    g1_fused<<<dim3(PP/128, BB), 256, G1F_SMEM>>>(b_g1, g1_gamma, g1_beta, g1_mean, g1_var, b_g2);
    gemm_mma<2><<<dim3(PP/128, 2, BB), 256, SMEM_GEMM>>>(b_out, o_gamma, o_beta, o_mean, o_var, x, out);
}

// round 13
// speedup vs baseline: 1.0124x; 1.0124x over previous
#include <cuda_runtime.h>
#include <cuda_bf16.h>
#include <math.h>
#include <stdint.h>

#define BB 4
#define CC 256
#define HH 64
#define WW 64
#define PP (HH*WW)
#define GG 4

// ---------------- device scratch ----------------
__device__ float g_offset[BB*18*PP];
__device__ float g_xdense[BB*CC*PP];
__device__ float g_Bxinf[(size_t)BB*PP*256];   // x, px-major fp32 (for sampling)

// bf16 hi/lo weights
__device__ __nv_bfloat16 g_Achi[256*512], g_Aclo[256*512];         // w_cross
__device__ __nv_bfloat16 g_Ag2hi[256*64], g_Ag2lo[256*64];         // w_g2
__device__ __nv_bfloat16 g_Aohi[256*256], g_Aolo[256*256];         // w_out
__device__ __nv_bfloat16 g_wdefhi[GG*64*9*64], g_wdeflo[GG*64*9*64];   // [g][co][k*64+cg] = [g][co][576]
__device__ __nv_bfloat16 g_w1hi[64*9*256],    g_w1lo[64*9*256];        // [co][k][ci]
__device__ __nv_bfloat16 g_woffhi[32*9*256],  g_wofflo[32*9*256];      // [co pad32][k][ci]
// bf16 hi/lo activation B-operands [px][ch]
__device__ __nv_bfloat16 g_Bchi[(size_t)BB*PP*512], g_Bclo[(size_t)BB*PP*512];   // cross in
__device__ __nv_bfloat16 g_Bxhi[(size_t)BB*PP*256], g_Bxlo[(size_t)BB*PP*256];   // xdense
__device__ __nv_bfloat16 g_Bohi[(size_t)BB*PP*256], g_Bolo[(size_t)BB*PP*256];   // xdense*attn
__device__ __nv_bfloat16 g_Bxinhi[(size_t)BB*PP*256], g_Bxinlo[(size_t)BB*PP*256]; // x
// deform sampled columns: [(b*GG+g)*PP+px][k*64+cg]
__device__ __nv_bfloat16 g_Bdhi[(size_t)BB*GG*PP*576], g_Bdlo[(size_t)BB*GG*PP*576];

__device__ __forceinline__ float sigm(float v){ return 1.0f/(1.0f+expf(-v)); }

__device__ __forceinline__ void split2(float v, __nv_bfloat16 &h, __nv_bfloat16 &l){
    h = __float2bfloat16(v);
    l = __float2bfloat16(v - __bfloat162float(h));
}
__device__ __forceinline__ uint32_t pack_bf(__nv_bfloat16 lo, __nv_bfloat16 hi){
    return (uint32_t)__bfloat16_as_ushort(lo) | ((uint32_t)__bfloat16_as_ushort(hi) << 16);
}

__device__ __forceinline__ uint32_t smem_u32(const void* p){
    uint32_t a;
    asm("{ .reg .u64 tmp; cvta.to.shared.u64 tmp, %1; cvt.u32.u64 %0, tmp; }" : "=r"(a) : "l"(p));
    return a;
}

#define LDSM_X4(r, addr) \
    asm volatile("ldmatrix.sync.aligned.m8n8.x4.shared.b16 {%0,%1,%2,%3}, [%4];" \
        : "=r"((r)[0]), "=r"((r)[1]), "=r"((r)[2]), "=r"((r)[3]) : "r"(addr))
#define LDSM_X2(r, addr) \
    asm volatile("ldmatrix.sync.aligned.m8n8.x2.shared.b16 {%0,%1}, [%2];" \
        : "=r"((r)[0]), "=r"((r)[1]) : "r"(addr))
#define MMA16816(d, a, bfr) \
    asm volatile("mma.sync.aligned.m16n8k16.row.col.f32.bf16.bf16.f32 " \
        "{%0,%1,%2,%3}, {%4,%5,%6,%7}, {%8,%9}, {%0,%1,%2,%3};" \
        : "+f"((d)[0]), "+f"((d)[1]), "+f"((d)[2]), "+f"((d)[3]) \
        : "r"((a)[0]), "r"((a)[1]), "r"((a)[2]), "r"((a)[3]), "r"((bfr)[0]), "r"((bfr)[1]))

#define CP16(dst, src) \
    asm volatile("cp.async.cg.shared.global [%0], [%1], 16;" :: "r"(dst), "l"(src))
#define CP_COMMIT() asm volatile("cp.async.commit_group;" ::: "memory")
#define CP_WAIT0()  asm volatile("cp.async.wait_group 0;" ::: "memory")

// ---------------- merged weight split ----------------
__global__ void split_all(const float* __restrict__ w_cross,
                          const float* __restrict__ w_g2,
                          const float* __restrict__ w_out,
                          const float* __restrict__ w_def,
                          const float* __restrict__ w_g1,
                          const float* __restrict__ w_off){
    int id = blockIdx.x*256 + threadIdx.x;
    if (id < 131072){
        split2(w_cross[id], g_Achi[id], g_Aclo[id]); return;
    }
    id -= 131072;
    if (id < 16384){
        split2(w_g2[id], g_Ag2hi[id], g_Ag2lo[id]); return;
    }
    id -= 16384;
    if (id < 65536){
        split2(w_out[id], g_Aohi[id], g_Aolo[id]); return;
    }
    id -= 65536;
    if (id < 147456){
        int cg = id & 63;
        int r  = id >> 6;
        int k  = r % 9;
        int r2 = r / 9;
        int co = r2 & 63;
        int g  = r2 >> 6;
        split2(w_def[((g*64 + co)*64 + cg)*9 + k], g_wdefhi[id], g_wdeflo[id]);
        return;
    }
    id -= 147456;
    if (id < 147456){
        int ci = id & 255;
        int r  = id >> 8;
        int k  = r % 9;
        int co = r / 9;
        split2(w_g1[(co*256 + ci)*9 + k], g_w1hi[id], g_w1lo[id]);
        return;
    }
    id -= 147456;
    if (id < 73728){
        int ci = id & 255;
        int r  = id >> 8;
        int k  = r % 9;
        int co = r / 9;
        float v = (co < 18) ? w_off[(co*256 + ci)*9 + k] : 0.f;
        split2(v, g_woffhi[id], g_wofflo[id]);
    }
}

// ---------------- merged converter: [ch][px] fp32 -> [px][ch] hi/lo (+fp32 for x) -------
__global__ __launch_bounds__(256) void conv_rows2(const float* __restrict__ x,
                                                  const float* __restrict__ x_prev){
    __shared__ float tile[32][33];
    int px0 = blockIdx.x*32;
    int ch0 = blockIdx.y*32;
    int bz  = blockIdx.z;
    int b   = (bz < BB) ? bz : bz - BB;
    const float* src = (bz < BB) ? x : x_prev;
    int t   = threadIdx.x;
    #pragma unroll
    for (int i=0;i<4;i++){
        int e = t + i*256;
        int r = e >> 5, c = e & 31;
        tile[r][c] = src[((size_t)(b*256+ch0+r))*PP + px0 + c];
    }
    __syncthreads();
    #pragma unroll
    for (int i=0;i<4;i++){
        int e = t + i*256;
        int r = e >> 5, c = e & 31;
        float v = tile[c][r];
        __nv_bfloat16 h, l;
        split2(v, h, l);
        if (bz < BB){
            size_t o = ((size_t)(b*PP) + px0 + r)*256 + ch0 + c;
            g_Bxinhi[o]=h; g_Bxinlo[o]=l;
            g_Bxinf[o]=v;
        } else {
            size_t o = ((size_t)(b*PP) + px0 + r)*512 + 256 + ch0 + c;
            g_Bchi[o]=h; g_Bclo[o]=l;
        }
    }
}

// ================= offset conv: halo-B implicit GEMM, 128-px tile =================
#define CB_BSZ 37008           // 257 rows * 144
#define OFFC_SMEM (4*32*144 + 2*CB_BSZ)   // 92448
__global__ __launch_bounds__(256) void off_mma(const float* __restrict__ b_off){
    constexpr int ASZ  = 32*144;   // 4608
    constexpr int BOFF = 4*ASZ;    // 18432
    extern __shared__ char sm[];
    uint32_t su = smem_u32(sm);
    int t = threadIdx.x, lane = t & 31, wid = t >> 5;
    int wn = wid;                 // 8 warps x 16 px
    int px0 = blockIdx.x*128;
    int b   = blockIdx.y;

    float acc[2][2][4];
    #pragma unroll
    for (int i=0;i<2;i++)
        #pragma unroll
        for (int j=0;j<2;j++)
            #pragma unroll
            for (int q=0;q<4;q++) acc[i][j][q]=0.f;

    int l16 = lane & 15;
    uint32_t aoff_base = (uint32_t)((lane & 15)*144 + ((lane >> 4) << 3)*2);
    uint32_t bcol = (uint32_t)((l16 >> 3)*16);
    int rr[2], ry[2], rxc[2];
    #pragma unroll
    for (int na=0;na<2;na++){
        int r = wn*16 + na*8 + (l16 & 7);
        rr[na] = r;
        ry[na]  = (px0 + r) >> 6;
        rxc[na] = (px0 + r) & 63;
    }

    if (t < 9)        *(uint4*)(sm + BOFF + 256*144 + t*16) = make_uint4(0,0,0,0);
    else if (t < 18)  *(uint4*)(sm + BOFF + CB_BSZ + 256*144 + (t-9)*16) = make_uint4(0,0,0,0);

    for (int sub=0; sub<4; sub++){
        __syncthreads();
        #pragma unroll
        for (int i=0;i<8;i++){
            int e = t + i*256;
            int rt = e >> 3, c8 = e & 7;
            int p = px0 - 64 + rt;
            if ((unsigned)p < (unsigned)PP){
                size_t rb = ((size_t)(b*PP) + p)*256 + sub*64 + c8*8;
                uint32_t so = (uint32_t)(rt*144 + c8*16);
                CP16(su + BOFF + so,          g_Bxinhi + rb);
                CP16(su + BOFF + CB_BSZ + so, g_Bxinlo + rb);
            }
        }
        {
            int r = t >> 3, c8 = t & 7;
            uint32_t so = (uint32_t)(r*144 + c8*16);
            size_t go = (size_t)r*2304 + sub*64 + c8*8;
            CP16(su + so,       g_woffhi + go);
            CP16(su + ASZ + so, g_wofflo + go);
        }
        CP_COMMIT();

        for (int k=0;k<9;k++){
            CP_WAIT0();
            __syncthreads();
            if (k < 8){
                int st = (k+1) & 1;
                int r = t >> 3, c8 = t & 7;
                uint32_t so = (uint32_t)(st*2*ASZ + r*144 + c8*16);
                size_t go = (size_t)r*2304 + (k+1)*256 + sub*64 + c8*8;
                CP16(su + so,       g_woffhi + go);
                CP16(su + ASZ + so, g_wofflo + go);
                CP_COMMIT();
            }
            int dy = k/3 - 1, dx = k%3 - 1;
            int off = dy*WW + dx;
            uint32_t brow[2];
            #pragma unroll
            for (int na=0;na<2;na++){
                int yy = ry[na] + dy, xx = rxc[na] + dx;
                bool v = ((unsigned)yy < HH) && ((unsigned)xx < WW);
                brow[na] = v ? (uint32_t)((rr[na] + 64 + off)*144) : (uint32_t)(256*144);
            }
            uint32_t abase = su + (uint32_t)((k&1)*2*ASZ) + aoff_base;
            #pragma unroll
            for (int ks=0;ks<4;ks++){
                uint32_t bh[2][2], bl[2][2];
                #pragma unroll
                for (int na=0;na<2;na++){
                    uint32_t ba = su + BOFF + brow[na] + bcol + ks*32;
                    LDSM_X2(bh[na], ba);
                    LDSM_X2(bl[na], ba + CB_BSZ);
                }
                #pragma unroll
                for (int ma=0;ma<2;ma++){
                    uint32_t ao = abase + (uint32_t)(ma*16*144 + ks*32);
                    uint32_t ah[4], al[4];
                    LDSM_X4(ah, ao);
                    LDSM_X4(al, ao + ASZ);
                    #pragma unroll
                    for (int na=0;na<2;na++){
                        MMA16816(acc[ma][na], ah, bh[na]);
                        MMA16816(acc[ma][na], al, bh[na]);
                        MMA16816(acc[ma][na], ah, bl[na]);
                    }
                }
            }
        }
    }

    #pragma unroll
    for (int ma=0;ma<2;ma++){
        int r0 = ma*16 + (lane>>2);
        int r1 = r0 + 8;
        #pragma unroll
        for (int na=0;na<2;na++){
            int px = px0 + wn*16 + na*8 + ((lane&3)<<1);
            if (r0 < 18){
                float bb = b_off[r0];
                *(float2*)&g_offset[((size_t)(b*18 + r0))*PP + px] =
                    make_float2(acc[ma][na][0]+bb, acc[ma][na][1]+bb);
            }
            if (r1 < 18){
                float bb = b_off[r1];
                *(float2*)&g_offset[((size_t)(b*18 + r1))*PP + px] =
                    make_float2(acc[ma][na][2]+bb, acc[ma][na][3]+bb);
            }
        }
    }
}

// ================= deform sampling: 16 threads/px, 4 ch each (1 float4 per corner) =======
__global__ __launch_bounds__(256) void sample_def(){
    int t = threadIdx.x;
    int pxl = t >> 4, c4 = t & 15;
    int px0 = blockIdx.x*16;
    int k  = blockIdx.y;
    int gz = blockIdx.z;
    int g = gz & 3, b = gz >> 2;
    int px = px0 + pxl;
    int y = px >> 6, xc = px & 63;

    float dy = g_offset[(b*18 + 2*k  )*PP + px];
    float dx = g_offset[(b*18 + 2*k+1)*PP + px];
    float py  = (float)y  + (float)(k/3 - 1) + dy;
    float pxx = (float)xc + (float)(k%3 - 1) + dx;
    float fy = floorf(py), fx = floorf(pxx);
    int y0 = (int)fy, x0 = (int)fx;
    float wy = py - fy, wx = pxx - fx;
    float w00 = (1.f-wy)*(1.f-wx);
    float w01 = (1.f-wy)*wx;
    float w10 = wy*(1.f-wx);
    float w11 = wy*wx;
    bool vy0 = (y0 >= 0) && (y0 < HH);
    bool vy1 = (y0 >= -1) && (y0 < HH-1);
    bool vx0 = (x0 >= 0) && (x0 < WW);
    bool vx1 = (x0 >= -1) && (x0 < WW-1);
    float m00 = (vy0 && vx0) ? w00 : 0.f;
    float m01 = (vy0 && vx1) ? w01 : 0.f;
    float m10 = (vy1 && vx0) ? w10 : 0.f;
    float m11 = (vy1 && vx1) ? w11 : 0.f;
    int cy0 = min(max(y0,0),HH-1), cy1 = min(max(y0+1,0),HH-1);
    int cx0 = min(max(x0,0),WW-1), cx1 = min(max(x0+1,0),WW-1);
    const float* base = g_Bxinf + ((size_t)(b*PP))*256 + g*64 + c4*4;
    float4 a00 = *(const float4*)(base + (size_t)(cy0*WW+cx0)*256);
    float4 a01 = *(const float4*)(base + (size_t)(cy0*WW+cx1)*256);
    float4 a10 = *(const float4*)(base + (size_t)(cy1*WW+cx0)*256);
    float4 a11 = *(const float4*)(base + (size_t)(cy1*WW+cx1)*256);

    float v0 = m00*a00.x + m01*a01.x + m10*a10.x + m11*a11.x;
    float v1 = m00*a00.y + m01*a01.y + m10*a10.y + m11*a11.y;
    float v2 = m00*a00.z + m01*a01.z + m10*a10.z + m11*a11.z;
    float v3 = m00*a00.w + m01*a01.w + m10*a10.w + m11*a11.w;

    __nv_bfloat16 h0,l0,h1,l1,h2,l2,h3,l3;
    split2(v0,h0,l0); split2(v1,h1,l1); split2(v2,h2,l2); split2(v3,h3,l3);
    uint2 hi = make_uint2(pack_bf(h0,h1), pack_bf(h2,h3));
    uint2 lo = make_uint2(pack_bf(l0,l1), pack_bf(l2,l3));

    size_t o = ((size_t)((b*GG+g)*PP) + px)*576 + k*64 + c4*4;
    *(uint2*)(g_Bdhi + o) = hi;
    *(uint2*)(g_Bdlo + o) = lo;
}

// ================= deform GEMM: 64co x 128px, K=576 (cp.async 2-stage) =================
#define DG_STAGE 55296
#define DG_SMEM (2*DG_STAGE)   // 110592

__device__ __forceinline__ void dg_copy(uint32_t su, int s, int c, int t,
    const __nv_bfloat16* Ab, const __nv_bfloat16* Alb,
    const __nv_bfloat16* Bb, const __nv_bfloat16* Blb){
    uint32_t base = su + s*DG_STAGE;
    #pragma unroll
    for (int i=0;i<2;i++){
        int e = t + i*256;
        int r = e >> 3, c8 = e & 7;
        uint32_t so = (uint32_t)(r*144 + c8*16);
        size_t go = (size_t)r*576 + c*64 + c8*8;
        CP16(base + so,        Ab  + go);
        CP16(base + 9216 + so, Alb + go);
    }
    #pragma unroll
    for (int i=0;i<4;i++){
        int e = t + i*256;
        int r = e >> 3, c8 = e & 7;
        uint32_t so = (uint32_t)(r*144 + c8*16);
        size_t go = (size_t)r*576 + c*64 + c8*8;
        CP16(base + 18432 + so, Bb  + go);
        CP16(base + 36864 + so, Blb + go);
    }
}

__global__ __launch_bounds__(256) void def_gemm(){
    extern __shared__ char sm[];
    uint32_t su = smem_u32(sm);
    int t = threadIdx.x, lane = t & 31, wid = t >> 5;
    int wm = wid >> 2, wn = wid & 3;
    int px0 = blockIdx.x*128;
    int g   = blockIdx.y;
    int b   = blockIdx.z;

    const __nv_bfloat16* Ab  = g_wdefhi + (size_t)g*64*576;
    const __nv_bfloat16* Alb = g_wdeflo + (size_t)g*64*576;
    const __nv_bfloat16* Bb  = g_Bdhi + ((size_t)((b*GG+g)*PP) + px0)*576;
    const __nv_bfloat16* Blb = g_Bdlo + ((size_t)((b*GG+g)*PP) + px0)*576;

    float acc[2][4][4];
    #pragma unroll
    for (int i=0;i<2;i++)
        #pragma unroll
        for (int j=0;j<4;j++)
            #pragma unroll
            for (int q=0;q<4;q++) acc[i][j][q]=0.f;

    int l16 = lane & 15;
    uint32_t aoff_base = (uint32_t)((wm*32 + (lane & 15))*144 + ((lane >> 4) << 3)*2);
    uint32_t boff_base = (uint32_t)((wn*32 + (l16 & 7))*144 + ((l16 >> 3) << 3)*2);

    dg_copy(su, 0, 0, t, Ab, Alb, Bb, Blb);
    CP_COMMIT();

    for (int c = 0; c < 9; c++){
        CP_WAIT0();
        __syncthreads();
        if (c+1 < 9){ dg_copy(su, (c+1)&1, c+1, t, Ab, Alb, Bb, Blb); CP_COMMIT(); }
        uint32_t sb = su + (c&1)*DG_STAGE;
        #pragma unroll
        for (int ks=0;ks<4;ks++){
            uint32_t bh[4][2], bl[4][2];
            #pragma unroll
            for (int na=0;na<4;na++){
                uint32_t boff = boff_base + (uint32_t)(na*8*144 + ks*32);
                LDSM_X2(bh[na], sb + 18432 + boff);
                LDSM_X2(bl[na], sb + 36864 + boff);
            }
            #pragma unroll
            for (int ma=0;ma<2;ma++){
                uint32_t ao = sb + aoff_base + (uint32_t)(ma*16*144 + ks*32);
                uint32_t ah[4], al[4];
                LDSM_X4(ah, ao);
                LDSM_X4(al, ao + 9216);
                #pragma unroll
                for (int na=0;na<4;na++){
                    MMA16816(acc[ma][na], ah, bh[na]);
                    MMA16816(acc[ma][na], al, bh[na]);
                    MMA16816(acc[ma][na], ah, bl[na]);
                }
            }
        }
    }

    // epilogue: transpose to [px][64] hi/lo in smem, write g_Bc slice [g*64, g*64+64)
    __syncthreads();
    #pragma unroll
    for (int ma=0;ma<2;ma++){
        int r0 = wm*32 + ma*16 + (lane>>2);
        int r1 = r0 + 8;
        #pragma unroll
        for (int na=0;na<4;na++){
            int px = wn*32 + na*8 + ((lane&3)<<1);
            __nv_bfloat16 h,l;
            split2(acc[ma][na][0],h,l);
            *(__nv_bfloat16*)(sm + px*144 + r0*2) = h;
            *(__nv_bfloat16*)(sm + 18432 + px*144 + r0*2) = l;
            split2(acc[ma][na][1],h,l);
            *(__nv_bfloat16*)(sm + (px+1)*144 + r0*2) = h;
            *(__nv_bfloat16*)(sm + 18432 + (px+1)*144 + r0*2) = l;
            split2(acc[ma][na][2],h,l);
            *(__nv_bfloat16*)(sm + px*144 + r1*2) = h;
            *(__nv_bfloat16*)(sm + 18432 + px*144 + r1*2) = l;
            split2(acc[ma][na][3],h,l);
            *(__nv_bfloat16*)(sm + (px+1)*144 + r1*2) = h;
            *(__nv_bfloat16*)(sm + 18432 + (px+1)*144 + r1*2) = l;
        }
    }
    __syncthreads();
    #pragma unroll
    for (int i=0;i<4;i++){
        int e = t + i*256;
        int r = e >> 3, c8 = e & 7;
        size_t o = ((size_t)(b*PP) + px0 + r)*512 + g*64 + c8*8;
        *(uint4*)(g_Bchi + o) = *(const uint4*)(sm + r*144 + c8*16);
        *(uint4*)(g_Bclo + o) = *(const uint4*)(sm + 18432 + r*144 + c8*16);
    }
}

// ---------------- generic mma GEMM (cp.async 2-stage) 128co x 128px ----------------
#define T_BYTES  (128*144)              // 18432
#define G_STAGE  (4*T_BYTES)            // 73728
#define SMEM_GEMM (2*G_STAGE)           // 147456

template<int K>
__device__ __forceinline__ void gemm_copy(uint32_t su, int s, int c, int t,
    const __nv_bfloat16* Ab, const __nv_bfloat16* Alb,
    const __nv_bfloat16* Bb, const __nv_bfloat16* Blb){
    uint32_t base = su + s*G_STAGE;
    #pragma unroll
    for (int i=0;i<4;i++){
        int e = t + i*256;
        int r = e >> 3, c8 = e & 7;
        uint32_t so = (uint32_t)(r*144 + c8*16);
        size_t go = (size_t)r*K + c*64 + c8*8;
        CP16(base + so,             Ab  + go);
        CP16(base + T_BYTES + so,   Alb + go);
        CP16(base + 2*T_BYTES + so, Bb  + go);
        CP16(base + 3*T_BYTES + so, Blb + go);
    }
}

template<int MODE>
__global__ __launch_bounds__(256) void gemm_mma(const float* __restrict__ bias,
                                                const float* __restrict__ gamma,
                                                const float* __restrict__ beta,
                                                const float* __restrict__ mean,
                                                const float* __restrict__ var,
                                                const float* __restrict__ resid,
                                                float* __restrict__ outp){
    constexpr int K = (MODE==0) ? 512 : 256;
    constexpr int CHUNKS = K/64;
    extern __shared__ char smem[];
    uint32_t su = smem_u32(smem);
    int t    = threadIdx.x;
    int lane = t & 31;
    int wid  = t >> 5;
    int wm   = wid >> 2;
    int wn   = wid & 3;
    int px0  = blockIdx.x*128;
    int co0  = blockIdx.y*128;
    int b    = blockIdx.z;

    const __nv_bfloat16* Ahi = (MODE==0) ? g_Achi : g_Aohi;
    const __nv_bfloat16* Alo = (MODE==0) ? g_Aclo : g_Aolo;
    const __nv_bfloat16* Bhi = (MODE==0) ? g_Bchi : g_Bohi;
    const __nv_bfloat16* Blo = (MODE==0) ? g_Bclo : g_Bolo;

    const __nv_bfloat16* Ab  = Ahi + (size_t)co0*K;
    const __nv_bfloat16* Alb = Alo + (size_t)co0*K;
    const __nv_bfloat16* Bb  = Bhi + ((size_t)(b*PP) + px0)*K;
    const __nv_bfloat16* Blb = Blo + ((size_t)(b*PP) + px0)*K;

    float acc[4][4][4];
    #pragma unroll
    for (int i=0;i<4;i++)
        #pragma unroll
        for (int j=0;j<4;j++)
            #pragma unroll
            for (int q=0;q<4;q++) acc[i][j][q] = 0.f;

    int l16 = lane & 15;
    uint32_t aoff_base = (uint32_t)((wm*64 + (lane & 15))*144 + ((lane >> 4) << 3)*2);
    uint32_t boff_base = (uint32_t)((wn*32 + (l16 & 7))*144 + ((l16 >> 3) << 3)*2);

    gemm_copy<K>(su, 0, 0, t, Ab, Alb, Bb, Blb);
    CP_COMMIT();

    for (int c = 0; c < CHUNKS; c++){
        CP_WAIT0();
        __syncthreads();
        if (c+1 < CHUNKS){ gemm_copy<K>(su, (c+1)&1, c+1, t, Ab, Alb, Bb, Blb); CP_COMMIT(); }
        uint32_t sb = su + (c&1)*G_STAGE;
        #pragma unroll
        for (int ks = 0; ks < 4; ks++){
            uint32_t bh[4][2], bl[4][2];
            #pragma unroll
            for (int na=0;na<4;na++){
                uint32_t boff = boff_base + (uint32_t)(na*8*144 + ks*32);
                LDSM_X2(bh[na], sb + 2*T_BYTES + boff);
                LDSM_X2(bl[na], sb + 3*T_BYTES + boff);
            }
            #pragma unroll
            for (int ma=0;ma<4;ma++){
                uint32_t aoff = aoff_base + (uint32_t)(ma*16*144 + ks*32);
                uint32_t ah[4], al[4];
                LDSM_X4(ah, sb + aoff);
                LDSM_X4(al, sb + T_BYTES + aoff);
                #pragma unroll
                for (int na=0;na<4;na++){
                    MMA16816(acc[ma][na], ah, bh[na]);
                    MMA16816(acc[ma][na], al, bh[na]);
                    MMA16816(acc[ma][na], ah, bl[na]);
                }
            }
        }
    }

    if (MODE == 2){
        #pragma unroll
        for (int ma=0;ma<4;ma++){
            int r0 = co0 + wm*64 + ma*16 + (lane>>2);
            int r1 = r0 + 8;
            float bb0 = bias[r0], bb1 = bias[r1];
            float iv0 = gamma[r0]*rsqrtf(var[r0]+1e-5f), sh0 = beta[r0]-mean[r0]*iv0;
            float iv1 = gamma[r1]*rsqrtf(var[r1]+1e-5f), sh1 = beta[r1]-mean[r1]*iv1;
            #pragma unroll
            for (int na=0;na<4;na++){
                int px = px0 + wn*32 + na*8 + ((lane&3)<<1);
                size_t i0 = ((size_t)(b*CC + r0))*PP + px;
                size_t i1 = ((size_t)(b*CC + r1))*PP + px;
                float2 rv0 = *(const float2*)&resid[i0];
                float2 rv1 = *(const float2*)&resid[i1];
                float v0 = (acc[ma][na][0]+bb0)*iv0 + sh0;
                float v1 = (acc[ma][na][1]+bb0)*iv0 + sh0;
                float v2 = (acc[ma][na][2]+bb1)*iv1 + sh1;
                float v3 = (acc[ma][na][3]+bb1)*iv1 + sh1;
                *(float2*)&outp[i0] = make_float2(rv0.x + v0*sigm(v0), rv0.y + v1*sigm(v1));
                *(float2*)&outp[i1] = make_float2(rv1.x + v2*sigm(v2), rv1.y + v3*sigm(v3));
            }
        }
        return;
    }

    // MODE 0: write g_xdense fp32 + transposed bf16 hi/lo g_Bx slice
    __syncthreads();
    #pragma unroll
    for (int ma=0;ma<4;ma++){
        int r0 = wm*64 + ma*16 + (lane>>2);
        int r1 = r0 + 8;
        int gr0 = co0 + r0, gr1 = co0 + r1;
        #pragma unroll
        for (int na=0;na<4;na++){
            int px = wn*32 + na*8 + ((lane&3)<<1);
            float d0 = acc[ma][na][0], d1 = acc[ma][na][1];
            float d2 = acc[ma][na][2], d3 = acc[ma][na][3];
            size_t i0 = ((size_t)(b*CC + gr0))*PP + px0 + px;
            size_t i1 = ((size_t)(b*CC + gr1))*PP + px0 + px;
            *(float2*)&g_xdense[i0] = make_float2(d0, d1);
            *(float2*)&g_xdense[i1] = make_float2(d2, d3);
            __nv_bfloat16 h,l;
            split2(d0,h,l);
            *(__nv_bfloat16*)(smem + px*272 + r0*2) = h;
            *(__nv_bfloat16*)(smem + 34816 + px*272 + r0*2) = l;
            split2(d1,h,l);
            *(__nv_bfloat16*)(smem + (px+1)*272 + r0*2) = h;
            *(__nv_bfloat16*)(smem + 34816 + (px+1)*272 + r0*2) = l;
            split2(d2,h,l);
            *(__nv_bfloat16*)(smem + px*272 + r1*2) = h;
            *(__nv_bfloat16*)(smem + 34816 + px*272 + r1*2) = l;
            split2(d3,h,l);
            *(__nv_bfloat16*)(smem + (px+1)*272 + r1*2) = h;
            *(__nv_bfloat16*)(smem + 34816 + (px+1)*272 + r1*2) = l;
        }
    }
    __syncthreads();
    #pragma unroll
    for (int i=0;i<8;i++){
        int e = t + i*256;
        int r = e >> 4, c16 = e & 15;
        size_t o = ((size_t)(b*PP) + px0 + r)*256 + co0 + c16*8;
        *(uint4*)(g_Bxhi + o) = *(const uint4*)(smem + r*272 + c16*16);
        *(uint4*)(g_Bxlo + o) = *(const uint4*)(smem + 34816 + r*272 + c16*16);
    }
}

// ================ g1 conv + g2 attention fused ================
#define G1F_SMEM (4*64*144 + 2*CB_BSZ)   // 110880
__global__ __launch_bounds__(256) void g1_fused(const float* __restrict__ bias,
                                                const float* __restrict__ gamma,
                                                const float* __restrict__ beta,
                                                const float* __restrict__ mean,
                                                const float* __restrict__ var,
                                                const float* __restrict__ b_g2){
    constexpr int ASZ  = 64*144;   // 9216
    constexpr int BOFF = 4*ASZ;    // 36864
    extern __shared__ char sm[];
    uint32_t su = smem_u32(sm);
    int t = threadIdx.x, lane = t & 31, wid = t >> 5;
    int wm = wid >> 2, wn = wid & 3;
    int px0 = blockIdx.x*128;
    int b   = blockIdx.y;

    int l16 = lane & 15;
    uint32_t aoff_base = (uint32_t)((wm*32 + (lane & 15))*144 + ((lane >> 4) << 3)*2);
    uint32_t bcol = (uint32_t)((l16 >> 3)*16);
    int rr[4], ry[4], rxc[4];
    #pragma unroll
    for (int na=0;na<4;na++){
        int r = wn*32 + na*8 + (l16 & 7);
        rr[na] = r;
        ry[na]  = (px0 + r) >> 6;
        rxc[na] = (px0 + r) & 63;
    }

    float acc[2][4][4];
    #pragma unroll
    for (int i=0;i<2;i++)
        #pragma unroll
        for (int j=0;j<4;j++)
            #pragma unroll
            for (int q=0;q<4;q++) acc[i][j][q]=0.f;

    if (t < 9)        *(uint4*)(sm + BOFF + 256*144 + t*16) = make_uint4(0,0,0,0);
    else if (t < 18)  *(uint4*)(sm + BOFF + CB_BSZ + 256*144 + (t-9)*16) = make_uint4(0,0,0,0);

    for (int sub=0; sub<4; sub++){
        __syncthreads();
        #pragma unroll
        for (int i=0;i<8;i++){
            int e = t + i*256;
            int rt = e >> 3, c8 = e & 7;
            int p = px0 - 64 + rt;
            if ((unsigned)p < (unsigned)PP){
                size_t rb = ((size_t)(b*PP) + p)*256 + sub*64 + c8*8;
                uint32_t so = (uint32_t)(rt*144 + c8*16);
                CP16(su + BOFF + so,          g_Bxhi + rb);
                CP16(su + BOFF + CB_BSZ + so, g_Bxlo + rb);
            }
        }
        #pragma unroll
        for (int i=0;i<2;i++){
            int e = t + i*256;
            int r = e >> 3, c8 = e & 7;
            uint32_t so = (uint32_t)(r*144 + c8*16);
            size_t go = (size_t)r*2304 + sub*64 + c8*8;
            CP16(su + so,       g_w1hi + go);
            CP16(su + ASZ + so, g_w1lo + go);
        }
        CP_COMMIT();

        for (int k=0;k<9;k++){
            CP_WAIT0();
            __syncthreads();
            if (k < 8){
                int st = (k+1) & 1;
                #pragma unroll
                for (int i=0;i<2;i++){
                    int e = t + i*256;
                    int r = e >> 3, c8 = e & 7;
                    uint32_t so = (uint32_t)(st*2*ASZ + r*144 + c8*16);
                    size_t go = (size_t)r*2304 + (k+1)*256 + sub*64 + c8*8;
                    CP16(su + so,       g_w1hi + go);
                    CP16(su + ASZ + so, g_w1lo + go);
                }
                CP_COMMIT();
            }
            int dy = k/3 - 1, dx = k%3 - 1;
            int off = dy*WW + dx;
            uint32_t brow[4];
            #pragma unroll
            for (int na=0;na<4;na++){
                int yy = ry[na] + dy, xx = rxc[na] + dx;
                bool v = ((unsigned)yy < HH) && ((unsigned)xx < WW);
                brow[na] = v ? (uint32_t)((rr[na] + 64 + off)*144) : (uint32_t)(256*144);
            }
            uint32_t abase = su + (uint32_t)((k&1)*2*ASZ) + aoff_base;
            #pragma unroll
            for (int ks=0;ks<4;ks++){
                uint32_t bh[4][2], bl[4][2];
                #pragma unroll
                for (int na=0;na<4;na++){
                    uint32_t ba = su + BOFF + brow[na] + bcol + ks*32;
                    LDSM_X2(bh[na], ba);
                    LDSM_X2(bl[na], ba + CB_BSZ);
                }
                #pragma unroll
                for (int ma=0;ma<2;ma++){
                    uint32_t ao = abase + (uint32_t)(ma*16*144 + ks*32);
                    uint32_t ah[4], al[4];
                    LDSM_X4(ah, ao);
                    LDSM_X4(al, ao + ASZ);
                    #pragma unroll
                    for (int na=0;na<4;na++){
                        MMA16816(acc[ma][na], ah, bh[na]);
                        MMA16816(acc[ma][na], al, bh[na]);
                        MMA16816(acc[ma][na], ah, bl[na]);
                    }
                }
            }
        }
    }

    // phase A epilogue: bn+silu -> a-tile staged at [0,36864) [px][64] hi/lo
    __syncthreads();
    #pragma unroll
    for (int ma=0;ma<2;ma++){
        int r0 = wm*32 + ma*16 + (lane>>2);
        int r1 = r0 + 8;
        float bb0 = bias[r0], bb1 = bias[r1];
        float iv0 = gamma[r0]*rsqrtf(var[r0]+1e-5f), sh0 = beta[r0]-mean[r0]*iv0;
        float iv1 = gamma[r1]*rsqrtf(var[r1]+1e-5f), sh1 = beta[r1]-mean[r1]*iv1;
        #pragma unroll
        for (int na=0;na<4;na++){
            int px = wn*32 + na*8 + ((lane&3)<<1);
            float v0 = (acc[ma][na][0]+bb0)*iv0 + sh0; v0 = v0*sigm(v0);
            float v1 = (acc[ma][na][1]+bb0)*iv0 + sh0; v1 = v1*sigm(v1);
            float v2 = (acc[ma][na][2]+bb1)*iv1 + sh1; v2 = v2*sigm(v2);
            float v3 = (acc[ma][na][3]+bb1)*iv1 + sh1; v3 = v3*sigm(v3);
            __nv_bfloat16 h,l;
            split2(v0,h,l);
            *(__nv_bfloat16*)(sm + px*144 + r0*2) = h;
            *(__nv_bfloat16*)(sm + 18432 + px*144 + r0*2) = l;
            split2(v1,h,l);
            *(__nv_bfloat16*)(sm + (px+1)*144 + r0*2) = h;
            *(__nv_bfloat16*)(sm + 18432 + (px+1)*144 + r0*2) = l;
            split2(v2,h,l);
            *(__nv_bfloat16*)(sm + px*144 + r1*2) = h;
            *(__nv_bfloat16*)(sm + 18432 + px*144 + r1*2) = l;
            split2(v3,h,l);
            *(__nv_bfloat16*)(sm + (px+1)*144 + r1*2) = h;
            *(__nv_bfloat16*)(sm + 18432 + (px+1)*144 + r1*2) = l;
        }
    }

    // ---- phase B: attn GEMM (K=64), 2 passes of 128 co ----
    uint32_t aoff2_base = (uint32_t)((wm*64 + (lane & 15))*144 + ((lane >> 4) << 3)*2);
    uint32_t boff2_base = (uint32_t)((wn*32 + (l16 & 7))*144 + ((l16 >> 3) << 3)*2);

    for (int p=0; p<2; p++){
        __syncthreads();
        #pragma unroll
        for (int i=0;i<4;i++){
            int e = t + i*256;
            int r = e >> 3, c8 = e & 7;
            uint32_t so = (uint32_t)(r*144 + c8*16);
            size_t go = (size_t)(p*128 + r)*64 + c8*8;
            CP16(su + BOFF + so,         g_Ag2hi + go);
            CP16(su + BOFF + 18432 + so, g_Ag2lo + go);
        }
        CP_COMMIT(); CP_WAIT0();
        __syncthreads();

        float acc2[4][4][4];
        #pragma unroll
        for (int i=0;i<4;i++)
            #pragma unroll
            for (int j=0;j<4;j++)
                #pragma unroll
                for (int q=0;q<4;q++) acc2[i][j][q]=0.f;

        #pragma unroll
        for (int ks=0;ks<4;ks++){
            uint32_t bh[4][2], bl[4][2];
            #pragma unroll
            for (int na=0;na<4;na++){
                uint32_t boff = boff2_base + (uint32_t)(na*8*144 + ks*32);
                LDSM_X2(bh[na], su + boff);
                LDSM_X2(bl[na], su + 18432 + boff);
            }
            #pragma unroll
            for (int ma=0;ma<4;ma++){
                uint32_t ao = su + BOFF + aoff2_base + (uint32_t)(ma*16*144 + ks*32);
                uint32_t ah[4], al[4];
                LDSM_X4(ah, ao);
                LDSM_X4(al, ao + 18432);
                #pragma unroll
                for (int na=0;na<4;na++){
                    MMA16816(acc2[ma][na], ah, bh[na]);
                    MMA16816(acc2[ma][na], al, bh[na]);
                    MMA16816(acc2[ma][na], ah, bl[na]);
                }
            }
        }

        __syncthreads();
        #pragma unroll
        for (int ma=0;ma<4;ma++){
            int r0 = wm*64 + ma*16 + (lane>>2);
            int r1 = r0 + 8;
            int gr0 = p*128 + r0, gr1 = p*128 + r1;
            float bb0 = b_g2[gr0], bb1 = b_g2[gr1];
            #pragma unroll
            for (int na=0;na<4;na++){
                int px = wn*32 + na*8 + ((lane&3)<<1);
                size_t i0 = ((size_t)(b*CC + gr0))*PP + px0 + px;
                size_t i1 = ((size_t)(b*CC + gr1))*PP + px0 + px;
                float2 x0 = *(const float2*)&g_xdense[i0];
                float2 x1 = *(const float2*)&g_xdense[i1];
                float v0 = x0.x * sigm(acc2[ma][na][0]+bb0);
                float v1 = x0.y * sigm(acc2[ma][na][1]+bb0);
                float v2 = x1.x * sigm(acc2[ma][na][2]+bb1);
                float v3 = x1.y * sigm(acc2[ma][na][3]+bb1);
                __nv_bfloat16 h,l;
                split2(v0,h,l);
                *(__nv_bfloat16*)(sm + BOFF + px*272 + r0*2) = h;
                *(__nv_bfloat16*)(sm + BOFF + 34816 + px*272 + r0*2) = l;
                split2(v1,h,l);
                *(__nv_bfloat16*)(sm + BOFF + (px+1)*272 + r0*2) = h;
                *(__nv_bfloat16*)(sm + BOFF + 34816 + (px+1)*272 + r0*2) = l;
                split2(v2,h,l);
                *(__nv_bfloat16*)(sm + BOFF + px*272 + r1*2) = h;
                *(__nv_bfloat16*)(sm + BOFF + 34816 + px*272 + r1*2) = l;
                split2(v3,h,l);
                *(__nv_bfloat16*)(sm + BOFF + (px+1)*272 + r1*2) = h;
                *(__nv_bfloat16*)(sm + BOFF + 34816 + (px+1)*272 + r1*2) = l;
            }
        }
        __syncthreads();
        #pragma unroll
        for (int i=0;i<8;i++){
            int e = t + i*256;
            int r = e >> 4, c16 = e & 15;
            size_t o = ((size_t)(b*PP) + px0 + r)*256 + p*128 + c16*8;
            *(uint4*)(g_Bohi + o) = *(const uint4*)(sm + BOFF + r*272 + c16*16);
            *(uint4*)(g_Bolo + o) = *(const uint4*)(sm + BOFF + 34816 + r*272 + c16*16);
        }
    }
}

// ---------------- launch ----------------
extern "C" void kernel_launch(void* const* d_in, const int* in_sizes, int n_in,
                              void* d_out, int out_size){
    const float* x       = (const float*)d_in[0];
    const float* x_prev  = (const float*)d_in[1];
    const float* w_off   = (const float*)d_in[2];
    const float* b_off   = (const float*)d_in[3];
    const float* w_def   = (const float*)d_in[4];
    const float* w_cross = (const float*)d_in[5];
    const float* w_g1    = (const float*)d_in[6];
    const float* b_g1    = (const float*)d_in[7];
    const float* g1_gamma= (const float*)d_in[8];
    const float* g1_beta = (const float*)d_in[9];
    const float* g1_mean = (const float*)d_in[10];
    const float* g1_var  = (const float*)d_in[11];
    const float* w_g2    = (const float*)d_in[12];
    const float* b_g2    = (const float*)d_in[13];
    const float* w_out   = (const float*)d_in[14];
    const float* b_out   = (const float*)d_in[15];
    const float* o_gamma = (const float*)d_in[16];
    const float* o_beta  = (const float*)d_in[17];
    const float* o_mean  = (const float*)d_in[18];
    const float* o_var   = (const float*)d_in[19];
    float* out = (float*)d_out;

    cudaFuncSetAttribute(gemm_mma<0>, cudaFuncAttributeMaxDynamicSharedMemorySize, SMEM_GEMM);
    cudaFuncSetAttribute(gemm_mma<2>, cudaFuncAttributeMaxDynamicSharedMemorySize, SMEM_GEMM);
    cudaFuncSetAttribute(def_gemm,    cudaFuncAttributeMaxDynamicSharedMemorySize, DG_SMEM);
    cudaFuncSetAttribute(off_mma,     cudaFuncAttributeMaxDynamicSharedMemorySize, OFFC_SMEM);
    cudaFuncSetAttribute(g1_fused,    cudaFuncAttributeMaxDynamicSharedMemorySize, G1F_SMEM);

    split_all<<<2272, 256>>>(w_cross, w_g2, w_out, w_def, w_g1, w_off);
    conv_rows2<<<dim3(PP/32, 8, 2*BB), 256>>>(x, x_prev);

    off_mma<<<dim3(PP/128, BB), 256, OFFC_SMEM>>>(b_off);
    sample_def<<<dim3(PP/16, 9, GG*BB), 256>>>();
    def_gemm<<<dim3(PP/128, GG, BB), 256, DG_SMEM>>>();

    gemm_mma<0><<<dim3(PP/128, 2, BB), 256, SMEM_GEMM>>>(nullptr,nullptr,nullptr,nullptr,nullptr,nullptr,nullptr);
    g1_fused<<<dim3(PP/128, BB), 256, G1F_SMEM>>>(b_g1, g1_gamma, g1_beta, g1_mean, g1_var, b_g2);
    gemm_mma<2><<<dim3(PP/128, 2, BB), 256, SMEM_GEMM>>>(b_out, o_gamma, o_beta, o_mean, o_var, x, out);
}

// round 14
// speedup vs baseline: 1.0221x; 1.0096x over previous
#include <cuda_runtime.h>
#include <cuda_bf16.h>
#include <math.h>
#include <stdint.h>

#define BB 4
#define CC 256
#define HH 64
#define WW 64
#define PP (HH*WW)
#define GG 4

// ---------------- device scratch ----------------
__device__ float g_offset[BB*18*PP];
__device__ float g_xdense[BB*CC*PP];
__device__ float g_Bxinf[(size_t)BB*PP*256];   // x, px-major fp32 (for sampling)

// bf16 hi/lo weights
__device__ __nv_bfloat16 g_Achi[256*512], g_Aclo[256*512];         // w_cross
__device__ __nv_bfloat16 g_Ag2hi[256*64], g_Ag2lo[256*64];         // w_g2
__device__ __nv_bfloat16 g_Aohi[256*256], g_Aolo[256*256];         // w_out
__device__ __nv_bfloat16 g_wdefhi[GG*64*9*64], g_wdeflo[GG*64*9*64];   // [g][co][k*64+cg] = [g][co][576]
__device__ __nv_bfloat16 g_w1hi[64*9*256],    g_w1lo[64*9*256];        // [co][k][ci]
__device__ __nv_bfloat16 g_woffhi[32*9*256],  g_wofflo[32*9*256];      // [co pad32][k][ci]
// bf16 hi/lo activation B-operands [px][ch]
__device__ __nv_bfloat16 g_Bchi[(size_t)BB*PP*512], g_Bclo[(size_t)BB*PP*512];   // cross in
__device__ __nv_bfloat16 g_Bxhi[(size_t)BB*PP*256], g_Bxlo[(size_t)BB*PP*256];   // xdense
__device__ __nv_bfloat16 g_Bohi[(size_t)BB*PP*256], g_Bolo[(size_t)BB*PP*256];   // xdense*attn
__device__ __nv_bfloat16 g_Bxinhi[(size_t)BB*PP*256], g_Bxinlo[(size_t)BB*PP*256]; // x
// deform sampled columns: [(b*GG+g)*PP+px][k*64+cg]
__device__ __nv_bfloat16 g_Bdhi[(size_t)BB*GG*PP*576], g_Bdlo[(size_t)BB*GG*PP*576];

__device__ __forceinline__ float sigm(float v){ return 1.0f/(1.0f+expf(-v)); }

__device__ __forceinline__ void split2(float v, __nv_bfloat16 &h, __nv_bfloat16 &l){
    h = __float2bfloat16(v);
    l = __float2bfloat16(v - __bfloat162float(h));
}
__device__ __forceinline__ uint32_t pack_bf(__nv_bfloat16 lo, __nv_bfloat16 hi){
    return (uint32_t)__bfloat16_as_ushort(lo) | ((uint32_t)__bfloat16_as_ushort(hi) << 16);
}

__device__ __forceinline__ uint32_t smem_u32(const void* p){
    uint32_t a;
    asm("{ .reg .u64 tmp; cvta.to.shared.u64 tmp, %1; cvt.u32.u64 %0, tmp; }" : "=r"(a) : "l"(p));
    return a;
}

#define LDSM_X4(r, addr) \
    asm volatile("ldmatrix.sync.aligned.m8n8.x4.shared.b16 {%0,%1,%2,%3}, [%4];" \
        : "=r"((r)[0]), "=r"((r)[1]), "=r"((r)[2]), "=r"((r)[3]) : "r"(addr))
#define LDSM_X2(r, addr) \
    asm volatile("ldmatrix.sync.aligned.m8n8.x2.shared.b16 {%0,%1}, [%2];" \
        : "=r"((r)[0]), "=r"((r)[1]) : "r"(addr))
#define MMA16816(d, a, bfr) \
    asm volatile("mma.sync.aligned.m16n8k16.row.col.f32.bf16.bf16.f32 " \
        "{%0,%1,%2,%3}, {%4,%5,%6,%7}, {%8,%9}, {%0,%1,%2,%3};" \
        : "+f"((d)[0]), "+f"((d)[1]), "+f"((d)[2]), "+f"((d)[3]) \
        : "r"((a)[0]), "r"((a)[1]), "r"((a)[2]), "r"((a)[3]), "r"((bfr)[0]), "r"((bfr)[1]))

#define CP16(dst, src) \
    asm volatile("cp.async.cg.shared.global [%0], [%1], 16;" :: "r"(dst), "l"(src))
#define CP_COMMIT() asm volatile("cp.async.commit_group;" ::: "memory")
#define CP_WAIT0()  asm volatile("cp.async.wait_group 0;" ::: "memory")

// ---------------- merged weight split ----------------
__global__ void split_all(const float* __restrict__ w_cross,
                          const float* __restrict__ w_g2,
                          const float* __restrict__ w_out,
                          const float* __restrict__ w_def,
                          const float* __restrict__ w_g1,
                          const float* __restrict__ w_off){
    int id = blockIdx.x*256 + threadIdx.x;
    if (id < 131072){
        split2(w_cross[id], g_Achi[id], g_Aclo[id]); return;
    }
    id -= 131072;
    if (id < 16384){
        split2(w_g2[id], g_Ag2hi[id], g_Ag2lo[id]); return;
    }
    id -= 16384;
    if (id < 65536){
        split2(w_out[id], g_Aohi[id], g_Aolo[id]); return;
    }
    id -= 65536;
    if (id < 147456){
        int cg = id & 63;
        int r  = id >> 6;
        int k  = r % 9;
        int r2 = r / 9;
        int co = r2 & 63;
        int g  = r2 >> 6;
        split2(w_def[((g*64 + co)*64 + cg)*9 + k], g_wdefhi[id], g_wdeflo[id]);
        return;
    }
    id -= 147456;
    if (id < 147456){
        int ci = id & 255;
        int r  = id >> 8;
        int k  = r % 9;
        int co = r / 9;
        split2(w_g1[(co*256 + ci)*9 + k], g_w1hi[id], g_w1lo[id]);
        return;
    }
    id -= 147456;
    if (id < 73728){
        int ci = id & 255;
        int r  = id >> 8;
        int k  = r % 9;
        int co = r / 9;
        float v = (co < 18) ? w_off[(co*256 + ci)*9 + k] : 0.f;
        split2(v, g_woffhi[id], g_wofflo[id]);
    }
}

// ---------------- merged converter: [ch][px] fp32 -> [px][ch] hi/lo (+fp32 for x) -------
__global__ __launch_bounds__(256) void conv_rows2(const float* __restrict__ x,
                                                  const float* __restrict__ x_prev){
    __shared__ float tile[32][33];
    int px0 = blockIdx.x*32;
    int ch0 = blockIdx.y*32;
    int bz  = blockIdx.z;
    int b   = (bz < BB) ? bz : bz - BB;
    const float* src = (bz < BB) ? x : x_prev;
    int t   = threadIdx.x;
    #pragma unroll
    for (int i=0;i<4;i++){
        int e = t + i*256;
        int r = e >> 5, c = e & 31;
        tile[r][c] = src[((size_t)(b*256+ch0+r))*PP + px0 + c];
    }
    __syncthreads();
    #pragma unroll
    for (int i=0;i<4;i++){
        int e = t + i*256;
        int r = e >> 5, c = e & 31;
        float v = tile[c][r];
        __nv_bfloat16 h, l;
        split2(v, h, l);
        if (bz < BB){
            size_t o = ((size_t)(b*PP) + px0 + r)*256 + ch0 + c;
            g_Bxinhi[o]=h; g_Bxinlo[o]=l;
            g_Bxinf[o]=v;
        } else {
            size_t o = ((size_t)(b*PP) + px0 + r)*512 + 256 + ch0 + c;
            g_Bchi[o]=h; g_Bclo[o]=l;
        }
    }
}

// ================= offset conv: halo-B implicit GEMM, 128-px tile =================
#define CB_BSZ 37008           // 257 rows * 144
#define OFFC_SMEM (4*32*144 + 2*CB_BSZ)   // 92448
__global__ __launch_bounds__(256) void off_mma(const float* __restrict__ b_off){
    constexpr int ASZ  = 32*144;   // 4608
    constexpr int BOFF = 4*ASZ;    // 18432
    extern __shared__ char sm[];
    uint32_t su = smem_u32(sm);
    int t = threadIdx.x, lane = t & 31, wid = t >> 5;
    int wn = wid;                 // 8 warps x 16 px
    int px0 = blockIdx.x*128;
    int b   = blockIdx.y;

    float acc[2][2][4];
    #pragma unroll
    for (int i=0;i<2;i++)
        #pragma unroll
        for (int j=0;j<2;j++)
            #pragma unroll
            for (int q=0;q<4;q++) acc[i][j][q]=0.f;

    int l16 = lane & 15;
    uint32_t aoff_base = (uint32_t)((lane & 15)*144 + ((lane >> 4) << 3)*2);
    uint32_t bcol = (uint32_t)((l16 >> 3)*16);
    int rr[2], ry[2], rxc[2];
    #pragma unroll
    for (int na=0;na<2;na++){
        int r = wn*16 + na*8 + (l16 & 7);
        rr[na] = r;
        ry[na]  = (px0 + r) >> 6;
        rxc[na] = (px0 + r) & 63;
    }

    if (t < 9)        *(uint4*)(sm + BOFF + 256*144 + t*16) = make_uint4(0,0,0,0);
    else if (t < 18)  *(uint4*)(sm + BOFF + CB_BSZ + 256*144 + (t-9)*16) = make_uint4(0,0,0,0);

    for (int sub=0; sub<4; sub++){
        __syncthreads();
        #pragma unroll
        for (int i=0;i<8;i++){
            int e = t + i*256;
            int rt = e >> 3, c8 = e & 7;
            int p = px0 - 64 + rt;
            if ((unsigned)p < (unsigned)PP){
                size_t rb = ((size_t)(b*PP) + p)*256 + sub*64 + c8*8;
                uint32_t so = (uint32_t)(rt*144 + c8*16);
                CP16(su + BOFF + so,          g_Bxinhi + rb);
                CP16(su + BOFF + CB_BSZ + so, g_Bxinlo + rb);
            }
        }
        {
            int r = t >> 3, c8 = t & 7;
            uint32_t so = (uint32_t)(r*144 + c8*16);
            size_t go = (size_t)r*2304 + sub*64 + c8*8;
            CP16(su + so,       g_woffhi + go);
            CP16(su + ASZ + so, g_wofflo + go);
        }
        CP_COMMIT();

        for (int k=0;k<9;k++){
            CP_WAIT0();
            __syncthreads();
            if (k < 8){
                int st = (k+1) & 1;
                int r = t >> 3, c8 = t & 7;
                uint32_t so = (uint32_t)(st*2*ASZ + r*144 + c8*16);
                size_t go = (size_t)r*2304 + (k+1)*256 + sub*64 + c8*8;
                CP16(su + so,       g_woffhi + go);
                CP16(su + ASZ + so, g_wofflo + go);
                CP_COMMIT();
            }
            int dy = k/3 - 1, dx = k%3 - 1;
            int off = dy*WW + dx;
            uint32_t brow[2];
            #pragma unroll
            for (int na=0;na<2;na++){
                int yy = ry[na] + dy, xx = rxc[na] + dx;
                bool v = ((unsigned)yy < HH) && ((unsigned)xx < WW);
                brow[na] = v ? (uint32_t)((rr[na] + 64 + off)*144) : (uint32_t)(256*144);
            }
            uint32_t abase = su + (uint32_t)((k&1)*2*ASZ) + aoff_base;
            #pragma unroll
            for (int ks=0;ks<4;ks++){
                uint32_t bh[2][2], bl[2][2];
                #pragma unroll
                for (int na=0;na<2;na++){
                    uint32_t ba = su + BOFF + brow[na] + bcol + ks*32;
                    LDSM_X2(bh[na], ba);
                    LDSM_X2(bl[na], ba + CB_BSZ);
                }
                #pragma unroll
                for (int ma=0;ma<2;ma++){
                    uint32_t ao = abase + (uint32_t)(ma*16*144 + ks*32);
                    uint32_t ah[4], al[4];
                    LDSM_X4(ah, ao);
                    LDSM_X4(al, ao + ASZ);
                    #pragma unroll
                    for (int na=0;na<2;na++){
                        MMA16816(acc[ma][na], ah, bh[na]);
                        MMA16816(acc[ma][na], al, bh[na]);
                        MMA16816(acc[ma][na], ah, bl[na]);
                    }
                }
            }
        }
    }

    #pragma unroll
    for (int ma=0;ma<2;ma++){
        int r0 = ma*16 + (lane>>2);
        int r1 = r0 + 8;
        #pragma unroll
        for (int na=0;na<2;na++){
            int px = px0 + wn*16 + na*8 + ((lane&3)<<1);
            if (r0 < 18){
                float bb = b_off[r0];
                *(float2*)&g_offset[((size_t)(b*18 + r0))*PP + px] =
                    make_float2(acc[ma][na][0]+bb, acc[ma][na][1]+bb);
            }
            if (r1 < 18){
                float bb = b_off[r1];
                *(float2*)&g_offset[((size_t)(b*18 + r1))*PP + px] =
                    make_float2(acc[ma][na][2]+bb, acc[ma][na][3]+bb);
            }
        }
    }
}

// ================= deform sampling: coords shared in smem, 16 threads/px =================
__global__ __launch_bounds__(256) void sample_def(){
    __shared__ float    s_m[16][4];
    __shared__ uint32_t s_r[16][4];
    int t = threadIdx.x;
    int px0 = blockIdx.x*16;
    int k  = blockIdx.y;
    int gz = blockIdx.z;
    int g = gz & 3, b = gz >> 2;

    if (t < 16){
        int px = px0 + t;
        int y = px >> 6, xc = px & 63;
        float dy = g_offset[(b*18 + 2*k  )*PP + px];
        float dx = g_offset[(b*18 + 2*k+1)*PP + px];
        float py  = (float)y  + (float)(k/3 - 1) + dy;
        float pxx = (float)xc + (float)(k%3 - 1) + dx;
        float fy = floorf(py), fx = floorf(pxx);
        int y0 = (int)fy, x0 = (int)fx;
        float wy = py - fy, wx = pxx - fx;
        float w00 = (1.f-wy)*(1.f-wx);
        float w01 = (1.f-wy)*wx;
        float w10 = wy*(1.f-wx);
        float w11 = wy*wx;
        bool vy0 = (y0 >= 0) && (y0 < HH);
        bool vy1 = (y0 >= -1) && (y0 < HH-1);
        bool vx0 = (x0 >= 0) && (x0 < WW);
        bool vx1 = (x0 >= -1) && (x0 < WW-1);
        s_m[t][0] = (vy0 && vx0) ? w00 : 0.f;
        s_m[t][1] = (vy0 && vx1) ? w01 : 0.f;
        s_m[t][2] = (vy1 && vx0) ? w10 : 0.f;
        s_m[t][3] = (vy1 && vx1) ? w11 : 0.f;
        int cy0 = min(max(y0,0),HH-1), cy1 = min(max(y0+1,0),HH-1);
        int cx0 = min(max(x0,0),WW-1), cx1 = min(max(x0+1,0),WW-1);
        s_r[t][0] = (uint32_t)(cy0*WW+cx0)*256u;
        s_r[t][1] = (uint32_t)(cy0*WW+cx1)*256u;
        s_r[t][2] = (uint32_t)(cy1*WW+cx0)*256u;
        s_r[t][3] = (uint32_t)(cy1*WW+cx1)*256u;
    }
    __syncthreads();

    int pxl = t >> 4, c4 = t & 15;
    float m00 = s_m[pxl][0], m01 = s_m[pxl][1], m10 = s_m[pxl][2], m11 = s_m[pxl][3];
    const float* base = g_Bxinf + (uint32_t)(b*PP)*256u + (uint32_t)(g*64 + c4*4);
    float4 a00 = *(const float4*)(base + s_r[pxl][0]);
    float4 a01 = *(const float4*)(base + s_r[pxl][1]);
    float4 a10 = *(const float4*)(base + s_r[pxl][2]);
    float4 a11 = *(const float4*)(base + s_r[pxl][3]);

    float v0 = m00*a00.x + m01*a01.x + m10*a10.x + m11*a11.x;
    float v1 = m00*a00.y + m01*a01.y + m10*a10.y + m11*a11.y;
    float v2 = m00*a00.z + m01*a01.z + m10*a10.z + m11*a11.z;
    float v3 = m00*a00.w + m01*a01.w + m10*a10.w + m11*a11.w;

    __nv_bfloat16 h0,l0,h1,l1,h2,l2,h3,l3;
    split2(v0,h0,l0); split2(v1,h1,l1); split2(v2,h2,l2); split2(v3,h3,l3);
    uint2 hi = make_uint2(pack_bf(h0,h1), pack_bf(h2,h3));
    uint2 lo = make_uint2(pack_bf(l0,l1), pack_bf(l2,l3));

    uint32_t o = ((uint32_t)((b*GG+g)*PP) + (uint32_t)(px0 + pxl))*576u + (uint32_t)(k*64 + c4*4);
    *(uint2*)(g_Bdhi + o) = hi;
    *(uint2*)(g_Bdlo + o) = lo;
}

// ================= deform GEMM: 64co x 128px, K=576 (cp.async 2-stage) =================
#define DG_STAGE 55296
#define DG_SMEM (2*DG_STAGE)   // 110592

__device__ __forceinline__ void dg_copy(uint32_t su, int s, int c, int t,
    const __nv_bfloat16* Ab, const __nv_bfloat16* Alb,
    const __nv_bfloat16* Bb, const __nv_bfloat16* Blb){
    uint32_t base = su + s*DG_STAGE;
    #pragma unroll
    for (int i=0;i<2;i++){
        int e = t + i*256;
        int r = e >> 3, c8 = e & 7;
        uint32_t so = (uint32_t)(r*144 + c8*16);
        size_t go = (size_t)r*576 + c*64 + c8*8;
        CP16(base + so,        Ab  + go);
        CP16(base + 9216 + so, Alb + go);
    }
    #pragma unroll
    for (int i=0;i<4;i++){
        int e = t + i*256;
        int r = e >> 3, c8 = e & 7;
        uint32_t so = (uint32_t)(r*144 + c8*16);
        size_t go = (size_t)r*576 + c*64 + c8*8;
        CP16(base + 18432 + so, Bb  + go);
        CP16(base + 36864 + so, Blb + go);
    }
}

__global__ __launch_bounds__(256) void def_gemm(){
    extern __shared__ char sm[];
    uint32_t su = smem_u32(sm);
    int t = threadIdx.x, lane = t & 31, wid = t >> 5;
    int wm = wid >> 2, wn = wid & 3;
    int px0 = blockIdx.x*128;
    int g   = blockIdx.y;
    int b   = blockIdx.z;

    const __nv_bfloat16* Ab  = g_wdefhi + (size_t)g*64*576;
    const __nv_bfloat16* Alb = g_wdeflo + (size_t)g*64*576;
    const __nv_bfloat16* Bb  = g_Bdhi + ((size_t)((b*GG+g)*PP) + px0)*576;
    const __nv_bfloat16* Blb = g_Bdlo + ((size_t)((b*GG+g)*PP) + px0)*576;

    float acc[2][4][4];
    #pragma unroll
    for (int i=0;i<2;i++)
        #pragma unroll
        for (int j=0;j<4;j++)
            #pragma unroll
            for (int q=0;q<4;q++) acc[i][j][q]=0.f;

    int l16 = lane & 15;
    uint32_t aoff_base = (uint32_t)((wm*32 + (lane & 15))*144 + ((lane >> 4) << 3)*2);
    uint32_t boff_base = (uint32_t)((wn*32 + (l16 & 7))*144 + ((l16 >> 3) << 3)*2);

    dg_copy(su, 0, 0, t, Ab, Alb, Bb, Blb);
    CP_COMMIT();

    for (int c = 0; c < 9; c++){
        CP_WAIT0();
        __syncthreads();
        if (c+1 < 9){ dg_copy(su, (c+1)&1, c+1, t, Ab, Alb, Bb, Blb); CP_COMMIT(); }
        uint32_t sb = su + (c&1)*DG_STAGE;
        #pragma unroll
        for (int ks=0;ks<4;ks++){
            uint32_t bh[4][2], bl[4][2];
            #pragma unroll
            for (int na=0;na<4;na++){
                uint32_t boff = boff_base + (uint32_t)(na*8*144 + ks*32);
                LDSM_X2(bh[na], sb + 18432 + boff);
                LDSM_X2(bl[na], sb + 36864 + boff);
            }
            #pragma unroll
            for (int ma=0;ma<2;ma++){
                uint32_t ao = sb + aoff_base + (uint32_t)(ma*16*144 + ks*32);
                uint32_t ah[4], al[4];
                LDSM_X4(ah, ao);
                LDSM_X4(al, ao + 9216);
                #pragma unroll
                for (int na=0;na<4;na++){
                    MMA16816(acc[ma][na], ah, bh[na]);
                    MMA16816(acc[ma][na], al, bh[na]);
                    MMA16816(acc[ma][na], ah, bl[na]);
                }
            }
        }
    }

    // epilogue: transpose to [px][64] hi/lo in smem, write g_Bc slice [g*64, g*64+64)
    __syncthreads();
    #pragma unroll
    for (int ma=0;ma<2;ma++){
        int r0 = wm*32 + ma*16 + (lane>>2);
        int r1 = r0 + 8;
        #pragma unroll
        for (int na=0;na<4;na++){
            int px = wn*32 + na*8 + ((lane&3)<<1);
            __nv_bfloat16 h,l;
            split2(acc[ma][na][0],h,l);
            *(__nv_bfloat16*)(sm + px*144 + r0*2) = h;
            *(__nv_bfloat16*)(sm + 18432 + px*144 + r0*2) = l;
            split2(acc[ma][na][1],h,l);
            *(__nv_bfloat16*)(sm + (px+1)*144 + r0*2) = h;
            *(__nv_bfloat16*)(sm + 18432 + (px+1)*144 + r0*2) = l;
            split2(acc[ma][na][2],h,l);
            *(__nv_bfloat16*)(sm + px*144 + r1*2) = h;
            *(__nv_bfloat16*)(sm + 18432 + px*144 + r1*2) = l;
            split2(acc[ma][na][3],h,l);
            *(__nv_bfloat16*)(sm + (px+1)*144 + r1*2) = h;
            *(__nv_bfloat16*)(sm + 18432 + (px+1)*144 + r1*2) = l;
        }
    }
    __syncthreads();
    #pragma unroll
    for (int i=0;i<4;i++){
        int e = t + i*256;
        int r = e >> 3, c8 = e & 7;
        size_t o = ((size_t)(b*PP) + px0 + r)*512 + g*64 + c8*8;
        *(uint4*)(g_Bchi + o) = *(const uint4*)(sm + r*144 + c8*16);
        *(uint4*)(g_Bclo + o) = *(const uint4*)(sm + 18432 + r*144 + c8*16);
    }
}

// ---------------- generic mma GEMM (cp.async 2-stage) 128co x 128px ----------------
#define T_BYTES  (128*144)              // 18432
#define G_STAGE  (4*T_BYTES)            // 73728
#define SMEM_GEMM (2*G_STAGE)           // 147456

template<int K>
__device__ __forceinline__ void gemm_copy(uint32_t su, int s, int c, int t,
    const __nv_bfloat16* Ab, const __nv_bfloat16* Alb,
    const __nv_bfloat16* Bb, const __nv_bfloat16* Blb){
    uint32_t base = su + s*G_STAGE;
    #pragma unroll
    for (int i=0;i<4;i++){
        int e = t + i*256;
        int r = e >> 3, c8 = e & 7;
        uint32_t so = (uint32_t)(r*144 + c8*16);
        size_t go = (size_t)r*K + c*64 + c8*8;
        CP16(base + so,             Ab  + go);
        CP16(base + T_BYTES + so,   Alb + go);
        CP16(base + 2*T_BYTES + so, Bb  + go);
        CP16(base + 3*T_BYTES + so, Blb + go);
    }
}

template<int MODE>
__global__ __launch_bounds__(256) void gemm_mma(const float* __restrict__ bias,
                                                const float* __restrict__ gamma,
                                                const float* __restrict__ beta,
                                                const float* __restrict__ mean,
                                                const float* __restrict__ var,
                                                const float* __restrict__ resid,
                                                float* __restrict__ outp){
    constexpr int K = (MODE==0) ? 512 : 256;
    constexpr int CHUNKS = K/64;
    extern __shared__ char smem[];
    uint32_t su = smem_u32(smem);
    int t    = threadIdx.x;
    int lane = t & 31;
    int wid  = t >> 5;
    int wm   = wid >> 2;
    int wn   = wid & 3;
    int px0  = blockIdx.x*128;
    int co0  = blockIdx.y*128;
    int b    = blockIdx.z;

    const __nv_bfloat16* Ahi = (MODE==0) ? g_Achi : g_Aohi;
    const __nv_bfloat16* Alo = (MODE==0) ? g_Aclo : g_Aolo;
    const __nv_bfloat16* Bhi = (MODE==0) ? g_Bchi : g_Bohi;
    const __nv_bfloat16* Blo = (MODE==0) ? g_Bclo : g_Bolo;

    const __nv_bfloat16* Ab  = Ahi + (size_t)co0*K;
    const __nv_bfloat16* Alb = Alo + (size_t)co0*K;
    const __nv_bfloat16* Bb  = Bhi + ((size_t)(b*PP) + px0)*K;
    const __nv_bfloat16* Blb = Blo + ((size_t)(b*PP) + px0)*K;

    float acc[4][4][4];
    #pragma unroll
    for (int i=0;i<4;i++)
        #pragma unroll
        for (int j=0;j<4;j++)
            #pragma unroll
            for (int q=0;q<4;q++) acc[i][j][q] = 0.f;

    int l16 = lane & 15;
    uint32_t aoff_base = (uint32_t)((wm*64 + (lane & 15))*144 + ((lane >> 4) << 3)*2);
    uint32_t boff_base = (uint32_t)((wn*32 + (l16 & 7))*144 + ((l16 >> 3) << 3)*2);

    gemm_copy<K>(su, 0, 0, t, Ab, Alb, Bb, Blb);
    CP_COMMIT();

    for (int c = 0; c < CHUNKS; c++){
        CP_WAIT0();
        __syncthreads();
        if (c+1 < CHUNKS){ gemm_copy<K>(su, (c+1)&1, c+1, t, Ab, Alb, Bb, Blb); CP_COMMIT(); }
        uint32_t sb = su + (c&1)*G_STAGE;
        #pragma unroll
        for (int ks = 0; ks < 4; ks++){
            uint32_t bh[4][2], bl[4][2];
            #pragma unroll
            for (int na=0;na<4;na++){
                uint32_t boff = boff_base + (uint32_t)(na*8*144 + ks*32);
                LDSM_X2(bh[na], sb + 2*T_BYTES + boff);
                LDSM_X2(bl[na], sb + 3*T_BYTES + boff);
            }
            #pragma unroll
            for (int ma=0;ma<4;ma++){
                uint32_t aoff = aoff_base + (uint32_t)(ma*16*144 + ks*32);
                uint32_t ah[4], al[4];
                LDSM_X4(ah, sb + aoff);
                LDSM_X4(al, sb + T_BYTES + aoff);
                #pragma unroll
                for (int na=0;na<4;na++){
                    MMA16816(acc[ma][na], ah, bh[na]);
                    MMA16816(acc[ma][na], al, bh[na]);
                    MMA16816(acc[ma][na], ah, bl[na]);
                }
            }
        }
    }

    if (MODE == 2){
        #pragma unroll
        for (int ma=0;ma<4;ma++){
            int r0 = co0 + wm*64 + ma*16 + (lane>>2);
            int r1 = r0 + 8;
            float bb0 = bias[r0], bb1 = bias[r1];
            float iv0 = gamma[r0]*rsqrtf(var[r0]+1e-5f), sh0 = beta[r0]-mean[r0]*iv0;
            float iv1 = gamma[r1]*rsqrtf(var[r1]+1e-5f), sh1 = beta[r1]-mean[r1]*iv1;
            #pragma unroll
            for (int na=0;na<4;na++){
                int px = px0 + wn*32 + na*8 + ((lane&3)<<1);
                size_t i0 = ((size_t)(b*CC + r0))*PP + px;
                size_t i1 = ((size_t)(b*CC + r1))*PP + px;
                float2 rv0 = *(const float2*)&resid[i0];
                float2 rv1 = *(const float2*)&resid[i1];
                float v0 = (acc[ma][na][0]+bb0)*iv0 + sh0;
                float v1 = (acc[ma][na][1]+bb0)*iv0 + sh0;
                float v2 = (acc[ma][na][2]+bb1)*iv1 + sh1;
                float v3 = (acc[ma][na][3]+bb1)*iv1 + sh1;
                *(float2*)&outp[i0] = make_float2(rv0.x + v0*sigm(v0), rv0.y + v1*sigm(v1));
                *(float2*)&outp[i1] = make_float2(rv1.x + v2*sigm(v2), rv1.y + v3*sigm(v3));
            }
        }
        return;
    }

    // MODE 0: write g_xdense fp32 + transposed bf16 hi/lo g_Bx slice
    __syncthreads();
    #pragma unroll
    for (int ma=0;ma<4;ma++){
        int r0 = wm*64 + ma*16 + (lane>>2);
        int r1 = r0 + 8;
        int gr0 = co0 + r0, gr1 = co0 + r1;
        #pragma unroll
        for (int na=0;na<4;na++){
            int px = wn*32 + na*8 + ((lane&3)<<1);
            float d0 = acc[ma][na][0], d1 = acc[ma][na][1];
            float d2 = acc[ma][na][2], d3 = acc[ma][na][3];
            size_t i0 = ((size_t)(b*CC + gr0))*PP + px0 + px;
            size_t i1 = ((size_t)(b*CC + gr1))*PP + px0 + px;
            *(float2*)&g_xdense[i0] = make_float2(d0, d1);
            *(float2*)&g_xdense[i1] = make_float2(d2, d3);
            __nv_bfloat16 h,l;
            split2(d0,h,l);
            *(__nv_bfloat16*)(smem + px*272 + r0*2) = h;
            *(__nv_bfloat16*)(smem + 34816 + px*272 + r0*2) = l;
            split2(d1,h,l);
            *(__nv_bfloat16*)(smem + (px+1)*272 + r0*2) = h;
            *(__nv_bfloat16*)(smem + 34816 + (px+1)*272 + r0*2) = l;
            split2(d2,h,l);
            *(__nv_bfloat16*)(smem + px*272 + r1*2) = h;
            *(__nv_bfloat16*)(smem + 34816 + px*272 + r1*2) = l;
            split2(d3,h,l);
            *(__nv_bfloat16*)(smem + (px+1)*272 + r1*2) = h;
            *(__nv_bfloat16*)(smem + 34816 + (px+1)*272 + r1*2) = l;
        }
    }
    __syncthreads();
    #pragma unroll
    for (int i=0;i<8;i++){
        int e = t + i*256;
        int r = e >> 4, c16 = e & 15;
        size_t o = ((size_t)(b*PP) + px0 + r)*256 + co0 + c16*8;
        *(uint4*)(g_Bxhi + o) = *(const uint4*)(smem + r*272 + c16*16);
        *(uint4*)(g_Bxlo + o) = *(const uint4*)(smem + 34816 + r*272 + c16*16);
    }
}

// ================ g1 conv + g2 attention fused ================
#define G1F_SMEM (4*64*144 + 2*CB_BSZ)   // 110880
__global__ __launch_bounds__(256) void g1_fused(const float* __restrict__ bias,
                                                const float* __restrict__ gamma,
                                                const float* __restrict__ beta,
                                                const float* __restrict__ mean,
                                                const float* __restrict__ var,
                                                const float* __restrict__ b_g2){
    constexpr int ASZ  = 64*144;   // 9216
    constexpr int BOFF = 4*ASZ;    // 36864
    extern __shared__ char sm[];
    uint32_t su = smem_u32(sm);
    int t = threadIdx.x, lane = t & 31, wid = t >> 5;
    int wm = wid >> 2, wn = wid & 3;
    int px0 = blockIdx.x*128;
    int b   = blockIdx.y;

    int l16 = lane & 15;
    uint32_t aoff_base = (uint32_t)((wm*32 + (lane & 15))*144 + ((lane >> 4) << 3)*2);
    uint32_t bcol = (uint32_t)((l16 >> 3)*16);
    int rr[4], ry[4], rxc[4];
    #pragma unroll
    for (int na=0;na<4;na++){
        int r = wn*32 + na*8 + (l16 & 7);
        rr[na] = r;
        ry[na]  = (px0 + r) >> 6;
        rxc[na] = (px0 + r) & 63;
    }

    float acc[2][4][4];
    #pragma unroll
    for (int i=0;i<2;i++)
        #pragma unroll
        for (int j=0;j<4;j++)
            #pragma unroll
            for (int q=0;q<4;q++) acc[i][j][q]=0.f;

    if (t < 9)        *(uint4*)(sm + BOFF + 256*144 + t*16) = make_uint4(0,0,0,0);
    else if (t < 18)  *(uint4*)(sm + BOFF + CB_BSZ + 256*144 + (t-9)*16) = make_uint4(0,0,0,0);

    for (int sub=0; sub<4; sub++){
        __syncthreads();
        #pragma unroll
        for (int i=0;i<8;i++){
            int e = t + i*256;
            int rt = e >> 3, c8 = e & 7;
            int p = px0 - 64 + rt;
            if ((unsigned)p < (unsigned)PP){
                size_t rb = ((size_t)(b*PP) + p)*256 + sub*64 + c8*8;
                uint32_t so = (uint32_t)(rt*144 + c8*16);
                CP16(su + BOFF + so,          g_Bxhi + rb);
                CP16(su + BOFF + CB_BSZ + so, g_Bxlo + rb);
            }
        }
        #pragma unroll
        for (int i=0;i<2;i++){
            int e = t + i*256;
            int r = e >> 3, c8 = e & 7;
            uint32_t so = (uint32_t)(r*144 + c8*16);
            size_t go = (size_t)r*2304 + sub*64 + c8*8;
            CP16(su + so,       g_w1hi + go);
            CP16(su + ASZ + so, g_w1lo + go);
        }
        CP_COMMIT();

        for (int k=0;k<9;k++){
            CP_WAIT0();
            __syncthreads();
            if (k < 8){
                int st = (k+1) & 1;
                #pragma unroll
                for (int i=0;i<2;i++){
                    int e = t + i*256;
                    int r = e >> 3, c8 = e & 7;
                    uint32_t so = (uint32_t)(st*2*ASZ + r*144 + c8*16);
                    size_t go = (size_t)r*2304 + (k+1)*256 + sub*64 + c8*8;
                    CP16(su + so,       g_w1hi + go);
                    CP16(su + ASZ + so, g_w1lo + go);
                }
                CP_COMMIT();
            }
            int dy = k/3 - 1, dx = k%3 - 1;
            int off = dy*WW + dx;
            uint32_t brow[4];
            #pragma unroll
            for (int na=0;na<4;na++){
                int yy = ry[na] + dy, xx = rxc[na] + dx;
                bool v = ((unsigned)yy < HH) && ((unsigned)xx < WW);
                brow[na] = v ? (uint32_t)((rr[na] + 64 + off)*144) : (uint32_t)(256*144);
            }
            uint32_t abase = su + (uint32_t)((k&1)*2*ASZ) + aoff_base;
            #pragma unroll
            for (int ks=0;ks<4;ks++){
                uint32_t bh[4][2], bl[4][2];
                #pragma unroll
                for (int na=0;na<4;na++){
                    uint32_t ba = su + BOFF + brow[na] + bcol + ks*32;
                    LDSM_X2(bh[na], ba);
                    LDSM_X2(bl[na], ba + CB_BSZ);
                }
                #pragma unroll
                for (int ma=0;ma<2;ma++){
                    uint32_t ao = abase + (uint32_t)(ma*16*144 + ks*32);
                    uint32_t ah[4], al[4];
                    LDSM_X4(ah, ao);
                    LDSM_X4(al, ao + ASZ);
                    #pragma unroll
                    for (int na=0;na<4;na++){
                        MMA16816(acc[ma][na], ah, bh[na]);
                        MMA16816(acc[ma][na], al, bh[na]);
                        MMA16816(acc[ma][na], ah, bl[na]);
                    }
                }
            }
        }
    }

    // phase A epilogue: bn+silu -> a-tile staged at [0,36864) [px][64] hi/lo
    __syncthreads();
    #pragma unroll
    for (int ma=0;ma<2;ma++){
        int r0 = wm*32 + ma*16 + (lane>>2);
        int r1 = r0 + 8;
        float bb0 = bias[r0], bb1 = bias[r1];
        float iv0 = gamma[r0]*rsqrtf(var[r0]+1e-5f), sh0 = beta[r0]-mean[r0]*iv0;
        float iv1 = gamma[r1]*rsqrtf(var[r1]+1e-5f), sh1 = beta[r1]-mean[r1]*iv1;
        #pragma unroll
        for (int na=0;na<4;na++){
            int px = wn*32 + na*8 + ((lane&3)<<1);
            float v0 = (acc[ma][na][0]+bb0)*iv0 + sh0; v0 = v0*sigm(v0);
            float v1 = (acc[ma][na][1]+bb0)*iv0 + sh0; v1 = v1*sigm(v1);
            float v2 = (acc[ma][na][2]+bb1)*iv1 + sh1; v2 = v2*sigm(v2);
            float v3 = (acc[ma][na][3]+bb1)*iv1 + sh1; v3 = v3*sigm(v3);
            __nv_bfloat16 h,l;
            split2(v0,h,l);
            *(__nv_bfloat16*)(sm + px*144 + r0*2) = h;
            *(__nv_bfloat16*)(sm + 18432 + px*144 + r0*2) = l;
            split2(v1,h,l);
            *(__nv_bfloat16*)(sm + (px+1)*144 + r0*2) = h;
            *(__nv_bfloat16*)(sm + 18432 + (px+1)*144 + r0*2) = l;
            split2(v2,h,l);
            *(__nv_bfloat16*)(sm + px*144 + r1*2) = h;
            *(__nv_bfloat16*)(sm + 18432 + px*144 + r1*2) = l;
            split2(v3,h,l);
            *(__nv_bfloat16*)(sm + (px+1)*144 + r1*2) = h;
            *(__nv_bfloat16*)(sm + 18432 + (px+1)*144 + r1*2) = l;
        }
    }

    // ---- phase B: attn GEMM (K=64), 2 passes of 128 co ----
    uint32_t aoff2_base = (uint32_t)((wm*64 + (lane & 15))*144 + ((lane >> 4) << 3)*2);
    uint32_t boff2_base = (uint32_t)((wn*32 + (l16 & 7))*144 + ((l16 >> 3) << 3)*2);

    for (int p=0; p<2; p++){
        __syncthreads();
        #pragma unroll
        for (int i=0;i<4;i++){
            int e = t + i*256;
            int r = e >> 3, c8 = e & 7;
            uint32_t so = (uint32_t)(r*144 + c8*16);
            size_t go = (size_t)(p*128 + r)*64 + c8*8;
            CP16(su + BOFF + so,         g_Ag2hi + go);
            CP16(su + BOFF + 18432 + so, g_Ag2lo + go);
        }
        CP_COMMIT(); CP_WAIT0();
        __syncthreads();

        float acc2[4][4][4];
        #pragma unroll
        for (int i=0;i<4;i++)
            #pragma unroll
            for (int j=0;j<4;j++)
                #pragma unroll
                for (int q=0;q<4;q++) acc2[i][j][q]=0.f;

        #pragma unroll
        for (int ks=0;ks<4;ks++){
            uint32_t bh[4][2], bl[4][2];
            #pragma unroll
            for (int na=0;na<4;na++){
                uint32_t boff = boff2_base + (uint32_t)(na*8*144 + ks*32);
                LDSM_X2(bh[na], su + boff);
                LDSM_X2(bl[na], su + 18432 + boff);
            }
            #pragma unroll
            for (int ma=0;ma<4;ma++){
                uint32_t ao = su + BOFF + aoff2_base + (uint32_t)(ma*16*144 + ks*32);
                uint32_t ah[4], al[4];
                LDSM_X4(ah, ao);
                LDSM_X4(al, ao + 18432);
                #pragma unroll
                for (int na=0;na<4;na++){
                    MMA16816(acc2[ma][na], ah, bh[na]);
                    MMA16816(acc2[ma][na], al, bh[na]);
                    MMA16816(acc2[ma][na], ah, bl[na]);
                }
            }
        }

        __syncthreads();
        #pragma unroll
        for (int ma=0;ma<4;ma++){
            int r0 = wm*64 + ma*16 + (lane>>2);
            int r1 = r0 + 8;
            int gr0 = p*128 + r0, gr1 = p*128 + r1;
            float bb0 = b_g2[gr0], bb1 = b_g2[gr1];
            #pragma unroll
            for (int na=0;na<4;na++){
                int px = wn*32 + na*8 + ((lane&3)<<1);
                size_t i0 = ((size_t)(b*CC + gr0))*PP + px0 + px;
                size_t i1 = ((size_t)(b*CC + gr1))*PP + px0 + px;
                float2 x0 = *(const float2*)&g_xdense[i0];
                float2 x1 = *(const float2*)&g_xdense[i1];
                float v0 = x0.x * sigm(acc2[ma][na][0]+bb0);
                float v1 = x0.y * sigm(acc2[ma][na][1]+bb0);
                float v2 = x1.x * sigm(acc2[ma][na][2]+bb1);
                float v3 = x1.y * sigm(acc2[ma][na][3]+bb1);
                __nv_bfloat16 h,l;
                split2(v0,h,l);
                *(__nv_bfloat16*)(sm + BOFF + px*272 + r0*2) = h;
                *(__nv_bfloat16*)(sm + BOFF + 34816 + px*272 + r0*2) = l;
                split2(v1,h,l);
                *(__nv_bfloat16*)(sm + BOFF + (px+1)*272 + r0*2) = h;
                *(__nv_bfloat16*)(sm + BOFF + 34816 + (px+1)*272 + r0*2) = l;
                split2(v2,h,l);
                *(__nv_bfloat16*)(sm + BOFF + px*272 + r1*2) = h;
                *(__nv_bfloat16*)(sm + BOFF + 34816 + px*272 + r1*2) = l;
                split2(v3,h,l);
                *(__nv_bfloat16*)(sm + BOFF + (px+1)*272 + r1*2) = h;
                *(__nv_bfloat16*)(sm + BOFF + 34816 + (px+1)*272 + r1*2) = l;
            }
        }
        __syncthreads();
        #pragma unroll
        for (int i=0;i<8;i++){
            int e = t + i*256;
            int r = e >> 4, c16 = e & 15;
            size_t o = ((size_t)(b*PP) + px0 + r)*256 + p*128 + c16*8;
            *(uint4*)(g_Bohi + o) = *(const uint4*)(sm + BOFF + r*272 + c16*16);
            *(uint4*)(g_Bolo + o) = *(const uint4*)(sm + BOFF + 34816 + r*272 + c16*16);
        }
    }
}

// ---------------- launch ----------------
extern "C" void kernel_launch(void* const* d_in, const int* in_sizes, int n_in,
                              void* d_out, int out_size){
    const float* x       = (const float*)d_in[0];
    const float* x_prev  = (const float*)d_in[1];
    const float* w_off   = (const float*)d_in[2];
    const float* b_off   = (const float*)d_in[3];
    const float* w_def   = (const float*)d_in[4];
    const float* w_cross = (const float*)d_in[5];
    const float* w_g1    = (const float*)d_in[6];
    const float* b_g1    = (const float*)d_in[7];
    const float* g1_gamma= (const float*)d_in[8];
    const float* g1_beta = (const float*)d_in[9];
    const float* g1_mean = (const float*)d_in[10];
    const float* g1_var  = (const float*)d_in[11];
    const float* w_g2    = (const float*)d_in[12];
    const float* b_g2    = (const float*)d_in[13];
    const float* w_out   = (const float*)d_in[14];
    const float* b_out   = (const float*)d_in[15];
    const float* o_gamma = (const float*)d_in[16];
    const float* o_beta  = (const float*)d_in[17];
    const float* o_mean  = (const float*)d_in[18];
    const float* o_var   = (const float*)d_in[19];
    float* out = (float*)d_out;

    cudaFuncSetAttribute(gemm_mma<0>, cudaFuncAttributeMaxDynamicSharedMemorySize, SMEM_GEMM);
    cudaFuncSetAttribute(gemm_mma<2>, cudaFuncAttributeMaxDynamicSharedMemorySize, SMEM_GEMM);
    cudaFuncSetAttribute(def_gemm,    cudaFuncAttributeMaxDynamicSharedMemorySize, DG_SMEM);
    cudaFuncSetAttribute(off_mma,     cudaFuncAttributeMaxDynamicSharedMemorySize, OFFC_SMEM);
    cudaFuncSetAttribute(g1_fused,    cudaFuncAttributeMaxDynamicSharedMemorySize, G1F_SMEM);

    split_all<<<2272, 256>>>(w_cross, w_g2, w_out, w_def, w_g1, w_off);
    conv_rows2<<<dim3(PP/32, 8, 2*BB), 256>>>(x, x_prev);

    off_mma<<<dim3(PP/128, BB), 256, OFFC_SMEM>>>(b_off);
    sample_def<<<dim3(PP/16, 9, GG*BB), 256>>>();
    def_gemm<<<dim3(PP/128, GG, BB), 256, DG_SMEM>>>();

    gemm_mma<0><<<dim3(PP/128, 2, BB), 256, SMEM_GEMM>>>(nullptr,nullptr,nullptr,nullptr,nullptr,nullptr,nullptr);
    g1_fused<<<dim3(PP/128, BB), 256, G1F_SMEM>>>(b_g1, g1_gamma, g1_beta, g1_mean, g1_var, b_g2);
    gemm_mma<2><<<dim3(PP/128, 2, BB), 256, SMEM_GEMM>>>(b_out, o_gamma, o_beta, o_mean, o_var, x, out);
}